// round 7
// baseline (speedup 1.0000x reference)
#include <cuda_runtime.h>
#include <cuda_bf16.h>
#include <stdint.h>

#define N_NODES 100000
#define E_EDGES 1600000
#define DIN 128
#define HID 64
#define DOUT 2

// Scratch (device globals; no allocation allowed)
__device__ int    g_hist[N_NODES];
__device__ int    g_rowstart[N_NODES + 1];
__device__ int    g_cursor[N_NODES];
__device__ int2   g_perm[E_EDGES];                 // {edge, src} sorted by dst
__device__ float  g_h[(size_t)N_NODES * HID];      // hidden activations
__device__ float4 g_tmp1[N_NODES];                 // {sum_p0, sum_p1, cnt, pad}

__device__ __forceinline__ void red_add_v4(float* addr, float a, float b, float c, float d) {
    asm volatile("red.global.add.v4.f32 [%0], {%1,%2,%3,%4};"
                 :: "l"(addr), "f"(a), "f"(b), "f"(c), "f"(d) : "memory");
}

__device__ __forceinline__ float4 ldcs4(const float4* p) {
    float4 v;
    asm volatile("ld.global.cs.v4.f32 {%0,%1,%2,%3}, [%4];"
                 : "=f"(v.x), "=f"(v.y), "=f"(v.z), "=f"(v.w) : "l"(p));
    return v;
}

// ---------------- binning: histogram over dst ----------------
__global__ void hist_kernel(const int* __restrict__ ei, int* __restrict__ hist, int E)
{
    int e = blockIdx.x * blockDim.x + threadIdx.x;
    if (e < E) atomicAdd(&hist[ei[E + e]], 1);
}

// ---------------- single-block exclusive scan ----------------
__global__ void scan_kernel(const int* __restrict__ hist,
                            int* __restrict__ rowstart, int* __restrict__ cursor,
                            int N, int E)
{
    __shared__ int warpsum[32];
    __shared__ int s_carry;
    int tid  = threadIdx.x;
    int lane = tid & 31;
    int wid  = tid >> 5;
    if (tid == 0) s_carry = 0;
    __syncthreads();

    int v = (tid < N) ? hist[tid] : 0;
    for (int base = 0; base < N; base += 1024) {
        int inext = base + 1024 + tid;
        int vnext = (inext < N && base + 1024 < N) ? hist[inext] : 0;

        int incl = v;
        #pragma unroll
        for (int off = 1; off < 32; off <<= 1) {
            int t = __shfl_up_sync(0xFFFFFFFFu, incl, off);
            if (lane >= off) incl += t;
        }
        if (lane == 31) warpsum[wid] = incl;
        __syncthreads();
        if (wid == 0) {
            int w = (lane < 32) ? warpsum[lane] : 0;
            int wi = w;
            #pragma unroll
            for (int off = 1; off < 32; off <<= 1) {
                int t = __shfl_up_sync(0xFFFFFFFFu, wi, off);
                if (lane >= off) wi += t;
            }
            warpsum[lane] = wi - w;
        }
        __syncthreads();
        int carry = s_carry;
        int excl = incl - v + warpsum[wid] + carry;
        int i = base + tid;
        if (i < N) { rowstart[i] = excl; cursor[i] = excl; }
        __syncthreads();
        if (tid == 1023) s_carry = excl + v;
        __syncthreads();
        v = vnext;
    }
    if (tid == 0) rowstart[N] = E;
}

__global__ void build_kernel(const int* __restrict__ ei, int* __restrict__ cursor,
                             int2* __restrict__ perm, int E)
{
    int e = blockIdx.x * blockDim.x + threadIdx.x;
    if (e >= E) return;
    int s = ei[e];
    int d = ei[E + e];
    int pos = atomicAdd(&cursor[d], 1);
    perm[pos] = make_int2(e, s);
}

// ---------------- fused layer 0: aggregate + GEMM + ReLU ----------------
// Block = 32 dst nodes, 256 threads. smem: W0 [256][64] (64KB) + f-tile [32][256] (32KB).
// Phase A: warp w aggregates dsts w*4..w*4+3; cooperative x staging.
// Phase B: 32x64 register-tiled GEMM, each thread 2 nodes x 4 oc.
__global__ void layer0_fused_kernel(const float* __restrict__ x,
                                    const float* __restrict__ ea,
                                    const int2* __restrict__ perm,
                                    const int* __restrict__ rowstart,
                                    const float* __restrict__ W0,
                                    const float* __restrict__ b0,
                                    float* __restrict__ h,
                                    int N)
{
    extern __shared__ float sm[];
    float* sW = sm;                 // [256][64]
    float* sF = sm + 2 * DIN * HID; // [32][256]

    int tid  = threadIdx.x;
    int lane = tid & 31;
    int wid  = tid >> 5;

    // stage W0 (coalesced float4)
    {
        const float4* w4 = reinterpret_cast<const float4*>(W0);
        float4* sw4 = reinterpret_cast<float4*>(sW);
        for (int i = tid; i < 2 * DIN * HID / 4; i += 256) sw4[i] = w4[i];
    }

    int base = blockIdx.x * 32;

    // stage x rows (coalesced): 32 nodes x 32 float4s
    for (int idx = tid; idx < 32 * 32; idx += 256) {
        int ln = idx >> 5;
        int kq = idx & 31;
        int node = base + ln;
        float4 v = make_float4(0.f, 0.f, 0.f, 0.f);
        if (node < N) v = reinterpret_cast<const float4*>(x + (long long)node * DIN)[kq];
        reinterpret_cast<float4*>(sF + ln * 256)[kq] = v;
    }

    // phase A: each warp aggregates 4 dsts
    for (int q = 0; q < 4; q++) {
        int ln = wid * 4 + q;
        int node = base + ln;
        if (node >= N) break;
        int beg = rowstart[node];
        int end = rowstart[node + 1];

        float4 acc = make_float4(0.f, 0.f, 0.f, 0.f);
        for (int b2 = beg; b2 < end; b2 += 32) {
            int take = min(end - b2, 32);
            int2 p = make_int2(0, 0);
            if (lane < take) p = perm[b2 + lane];

            int j = 0;
            for (; j + 4 <= take; j += 4) {
                int e0 = __shfl_sync(0xFFFFFFFFu, p.x, j + 0);
                int s0 = __shfl_sync(0xFFFFFFFFu, p.y, j + 0);
                int e1 = __shfl_sync(0xFFFFFFFFu, p.x, j + 1);
                int s1 = __shfl_sync(0xFFFFFFFFu, p.y, j + 1);
                int e2 = __shfl_sync(0xFFFFFFFFu, p.x, j + 2);
                int s2 = __shfl_sync(0xFFFFFFFFu, p.y, j + 2);
                int e3 = __shfl_sync(0xFFFFFFFFu, p.x, j + 3);
                int s3 = __shfl_sync(0xFFFFFFFFu, p.y, j + 3);

                float4 ev0 = ldcs4(reinterpret_cast<const float4*>(ea + (long long)e0 * DIN) + lane);
                float4 ev1 = ldcs4(reinterpret_cast<const float4*>(ea + (long long)e1 * DIN) + lane);
                float4 ev2 = ldcs4(reinterpret_cast<const float4*>(ea + (long long)e2 * DIN) + lane);
                float4 ev3 = ldcs4(reinterpret_cast<const float4*>(ea + (long long)e3 * DIN) + lane);
                float4 xv0 = reinterpret_cast<const float4*>(x + (long long)s0 * DIN)[lane];
                float4 xv1 = reinterpret_cast<const float4*>(x + (long long)s1 * DIN)[lane];
                float4 xv2 = reinterpret_cast<const float4*>(x + (long long)s2 * DIN)[lane];
                float4 xv3 = reinterpret_cast<const float4*>(x + (long long)s3 * DIN)[lane];

                acc.x = fmaf(xv0.x, ev0.x, acc.x); acc.y = fmaf(xv0.y, ev0.y, acc.y);
                acc.z = fmaf(xv0.z, ev0.z, acc.z); acc.w = fmaf(xv0.w, ev0.w, acc.w);
                acc.x = fmaf(xv1.x, ev1.x, acc.x); acc.y = fmaf(xv1.y, ev1.y, acc.y);
                acc.z = fmaf(xv1.z, ev1.z, acc.z); acc.w = fmaf(xv1.w, ev1.w, acc.w);
                acc.x = fmaf(xv2.x, ev2.x, acc.x); acc.y = fmaf(xv2.y, ev2.y, acc.y);
                acc.z = fmaf(xv2.z, ev2.z, acc.z); acc.w = fmaf(xv2.w, ev2.w, acc.w);
                acc.x = fmaf(xv3.x, ev3.x, acc.x); acc.y = fmaf(xv3.y, ev3.y, acc.y);
                acc.z = fmaf(xv3.z, ev3.z, acc.z); acc.w = fmaf(xv3.w, ev3.w, acc.w);
            }
            for (; j < take; j++) {
                int e = __shfl_sync(0xFFFFFFFFu, p.x, j);
                int s = __shfl_sync(0xFFFFFFFFu, p.y, j);
                float4 ev = ldcs4(reinterpret_cast<const float4*>(ea + (long long)e * DIN) + lane);
                float4 xv = reinterpret_cast<const float4*>(x + (long long)s * DIN)[lane];
                acc.x = fmaf(xv.x, ev.x, acc.x);
                acc.y = fmaf(xv.y, ev.y, acc.y);
                acc.z = fmaf(xv.z, ev.z, acc.z);
                acc.w = fmaf(xv.w, ev.w, acc.w);
            }
        }
        int deg = end - beg;
        float inv = (deg > 0) ? (1.0f / (float)deg) : 0.f;
        acc.x *= inv; acc.y *= inv; acc.z *= inv; acc.w *= inv;
        reinterpret_cast<float4*>(sF + ln * 256 + DIN)[lane] = acc;
    }
    __syncthreads();

    // phase B: GEMM 32 nodes x 64 oc; thread = 2 nodes x 4 oc
    int to = tid & 15;   // oc quad
    int tn = tid >> 4;   // node pair
    float c0[4] = {0.f, 0.f, 0.f, 0.f};
    float c1[4] = {0.f, 0.f, 0.f, 0.f};
    const float* fa0 = sF + (2 * tn + 0) * 256;
    const float* fa1 = sF + (2 * tn + 1) * 256;

    #pragma unroll 4
    for (int k = 0; k < 2 * DIN; k++) {
        float4 b = reinterpret_cast<const float4*>(sW + k * HID)[to];
        float a0 = fa0[k], a1 = fa1[k];
        c0[0] = fmaf(a0, b.x, c0[0]); c0[1] = fmaf(a0, b.y, c0[1]);
        c0[2] = fmaf(a0, b.z, c0[2]); c0[3] = fmaf(a0, b.w, c0[3]);
        c1[0] = fmaf(a1, b.x, c1[0]); c1[1] = fmaf(a1, b.y, c1[1]);
        c1[2] = fmaf(a1, b.z, c1[2]); c1[3] = fmaf(a1, b.w, c1[3]);
    }

    float4 bias = reinterpret_cast<const float4*>(b0)[to];
    {
        int node = base + 2 * tn;
        if (node < N) {
            float4 o;
            o.x = fmaxf(c0[0] + bias.x, 0.f);
            o.y = fmaxf(c0[1] + bias.y, 0.f);
            o.z = fmaxf(c0[2] + bias.z, 0.f);
            o.w = fmaxf(c0[3] + bias.w, 0.f);
            reinterpret_cast<float4*>(h + (long long)node * HID)[to] = o;
        }
        node++;
        if (node < N) {
            float4 o;
            o.x = fmaxf(c1[0] + bias.x, 0.f);
            o.y = fmaxf(c1[1] + bias.y, 0.f);
            o.z = fmaxf(c1[2] + bias.z, 0.f);
            o.w = fmaxf(c1[3] + bias.w, 0.f);
            reinterpret_cast<float4*>(h + (long long)node * HID)[to] = o;
        }
    }
}

// ---------------- layer 1: project-then-scatter ----------------
__global__ void edgeproj1_kernel(const float* __restrict__ h,
                                 const int* __restrict__ ei,
                                 const float* __restrict__ ea,
                                 const float* __restrict__ W1,
                                 float4* __restrict__ tmp,
                                 int E)
{
    __shared__ float sw[2 * HID]; // W1 rows 64..127
    if (threadIdx.x < 2 * HID) sw[threadIdx.x] = W1[2 * HID + threadIdx.x];
    __syncthreads();

    int warp = (blockIdx.x * blockDim.x + threadIdx.x) >> 5;
    int lane = threadIdx.x & 31;
    if (warp >= E) return;

    int s = ei[warp];
    int d = ei[E + warp];

    float2 hv = reinterpret_cast<const float2*>(h  + (long long)s * HID)[lane];
    float2 ev = reinterpret_cast<const float2*>(ea + (long long)warp * HID)[lane];
    float mx = hv.x * ev.x;
    float my = hv.y * ev.y;

    int k = 2 * lane;
    float a0 = mx * sw[k * 2 + 0] + my * sw[(k + 1) * 2 + 0];
    float a1 = mx * sw[k * 2 + 1] + my * sw[(k + 1) * 2 + 1];

    #pragma unroll
    for (int o = 16; o > 0; o >>= 1) {
        a0 += __shfl_xor_sync(0xFFFFFFFFu, a0, o);
        a1 += __shfl_xor_sync(0xFFFFFFFFu, a1, o);
    }
    if (lane == 0)
        red_add_v4(reinterpret_cast<float*>(tmp + d), a0, a1, 1.0f, 0.f);
}

// ---------------- layer 1 dense ----------------
__global__ void layer1_mm_kernel(const float* __restrict__ h,
                                 const float4* __restrict__ tmp,
                                 const float* __restrict__ W1,
                                 const float* __restrict__ b1,
                                 float* __restrict__ out,
                                 int N)
{
    __shared__ float sW[2 * HID];
    __shared__ float sb[DOUT];
    if (threadIdx.x < 2 * HID) sW[threadIdx.x] = W1[threadIdx.x];
    if (threadIdx.x < DOUT) sb[threadIdx.x] = b1[threadIdx.x];
    __syncthreads();

    int warp = (blockIdx.x * blockDim.x + threadIdx.x) >> 5;
    int lane = threadIdx.x & 31;
    if (warp >= N) return;

    long long rb = (long long)warp * HID;
    float h0 = h[rb + lane];
    float h1 = h[rb + 32 + lane];

    float acc0 = h0 * sW[lane * 2 + 0] + h1 * sW[(32 + lane) * 2 + 0];
    float acc1 = h0 * sW[lane * 2 + 1] + h1 * sW[(32 + lane) * 2 + 1];

    #pragma unroll
    for (int o = 16; o > 0; o >>= 1) {
        acc0 += __shfl_xor_sync(0xFFFFFFFFu, acc0, o);
        acc1 += __shfl_xor_sync(0xFFFFFFFFu, acc1, o);
    }
    if (lane == 0) {
        float4 t = tmp[warp];
        float inv = (t.z > 0.f) ? (1.0f / t.z) : 0.f;
        out[(long long)warp * DOUT + 0] = acc0 + t.x * inv + sb[0];
        out[(long long)warp * DOUT + 1] = acc1 + t.y * inv + sb[1];
    }
}

// ---------------------------------------------------------------------------
extern "C" void kernel_launch(void* const* d_in, const int* in_sizes, int n_in,
                              void* d_out, int out_size)
{
    const float* x   = (const float*)d_in[0];
    const int*   ei  = (const int*)d_in[1];
    const float* ea0 = (const float*)d_in[2];
    const float* ea1 = (const float*)d_in[3];
    const float* W0  = (const float*)d_in[4];
    const float* b0  = (const float*)d_in[5];
    const float* W1  = (const float*)d_in[6];
    const float* b1  = (const float*)d_in[7];
    float* out = (float*)d_out;

    const int N = in_sizes[0] / DIN;
    const int E = in_sizes[1] / 2;

    int *hist_p, *rowstart_p, *cursor_p;
    int2 *perm_p;
    float *h_p;
    float4 *tmp1_p;
    cudaGetSymbolAddress((void**)&hist_p,     g_hist);
    cudaGetSymbolAddress((void**)&rowstart_p, g_rowstart);
    cudaGetSymbolAddress((void**)&cursor_p,   g_cursor);
    cudaGetSymbolAddress((void**)&perm_p,     g_perm);
    cudaGetSymbolAddress((void**)&h_p,        g_h);
    cudaGetSymbolAddress((void**)&tmp1_p,     g_tmp1);

    // launches 0,1: memsets
    cudaMemsetAsync(hist_p, 0, (size_t)N * sizeof(int), 0);
    cudaMemsetAsync(tmp1_p, 0, (size_t)N * sizeof(float4), 0);

    // launch 2: histogram
    hist_kernel<<<(E + 255) / 256, 256>>>(ei, hist_p, E);
    // launch 3: scan
    scan_kernel<<<1, 1024>>>(hist_p, rowstart_p, cursor_p, N, E);
    // launch 4: perm build
    build_kernel<<<(E + 255) / 256, 256>>>(ei, cursor_p, perm_p, E);

    // launch 5: fused layer-0 (profiled by ncu -s 5 -c 1)
    {
        size_t smem = (size_t)(2 * DIN * HID + 32 * 2 * DIN) * sizeof(float); // 96KB
        cudaFuncSetAttribute(layer0_fused_kernel,
                             cudaFuncAttributeMaxDynamicSharedMemorySize, (int)smem);
        layer0_fused_kernel<<<(N + 31) / 32, 256, smem>>>(x, ea0, perm_p, rowstart_p,
                                                          W0, b0, h_p, N);
    }

    // launch 6: layer-1 edge projection + scatter
    edgeproj1_kernel<<<(E * 32 + 255) / 256, 256>>>(h_p, ei, ea1, W1, tmp1_p, E);
    // launch 7: layer-1 dense
    layer1_mm_kernel<<<(N * 32 + 255) / 256, 256>>>(h_p, tmp1_p, W1, b1, out, N);
}

// round 8
// speedup vs baseline: 1.7055x; 1.7055x over previous
#include <cuda_runtime.h>
#include <cuda_bf16.h>
#include <stdint.h>

#define N_NODES 100000
#define E_EDGES 1600000
#define DIN 128
#define HID 64
#define DOUT 2

// Scratch (device globals; no allocation allowed)
__device__ int    g_hist[N_NODES];
__device__ int    g_rowstart[N_NODES + 1];
__device__ int    g_cursor[N_NODES];
__device__ int2   g_perm[E_EDGES];                 // {edge, src} sorted by dst
__device__ float  g_agg0[(size_t)N_NODES * DIN];   // layer-0 MEAN aggregation
__device__ float  g_h[(size_t)N_NODES * HID];      // hidden activations
__device__ float4 g_tmp1[N_NODES];                 // {sum_p0, sum_p1, cnt, pad}

__device__ __forceinline__ void red_add_v4(float* addr, float a, float b, float c, float d) {
    asm volatile("red.global.add.v4.f32 [%0], {%1,%2,%3,%4};"
                 :: "l"(addr), "f"(a), "f"(b), "f"(c), "f"(d) : "memory");
}

__device__ __forceinline__ float4 ldcs4(const float4* p) {
    float4 v;
    asm volatile("ld.global.cs.v4.f32 {%0,%1,%2,%3}, [%4];"
                 : "=f"(v.x), "=f"(v.y), "=f"(v.z), "=f"(v.w) : "l"(p));
    return v;
}

// ---------------- histogram over dst (+ zero tmp1 on the side) ----------------
__global__ void hist_kernel(const int* __restrict__ ei, int* __restrict__ hist,
                            float4* __restrict__ tmp, int E, int N)
{
    int e = blockIdx.x * blockDim.x + threadIdx.x;
    if (e < N) tmp[e] = make_float4(0.f, 0.f, 0.f, 0.f);
    if (e < E) atomicAdd(&hist[ei[E + e]], 1);
}

// ---------------- single-block exclusive scan ----------------
__global__ void scan_kernel(const int* __restrict__ hist,
                            int* __restrict__ rowstart, int* __restrict__ cursor,
                            int N, int E)
{
    __shared__ int warpsum[32];
    __shared__ int s_carry;
    int tid  = threadIdx.x;
    int lane = tid & 31;
    int wid  = tid >> 5;
    if (tid == 0) s_carry = 0;
    __syncthreads();

    int v = (tid < N) ? hist[tid] : 0;
    for (int base = 0; base < N; base += 1024) {
        int inext = base + 1024 + tid;
        int vnext = (inext < N && base + 1024 < N) ? hist[inext] : 0;

        int incl = v;
        #pragma unroll
        for (int off = 1; off < 32; off <<= 1) {
            int t = __shfl_up_sync(0xFFFFFFFFu, incl, off);
            if (lane >= off) incl += t;
        }
        if (lane == 31) warpsum[wid] = incl;
        __syncthreads();
        if (wid == 0) {
            int w = (lane < 32) ? warpsum[lane] : 0;
            int wi = w;
            #pragma unroll
            for (int off = 1; off < 32; off <<= 1) {
                int t = __shfl_up_sync(0xFFFFFFFFu, wi, off);
                if (lane >= off) wi += t;
            }
            warpsum[lane] = wi - w;
        }
        __syncthreads();
        int carry = s_carry;
        int excl = incl - v + warpsum[wid] + carry;
        int i = base + tid;
        if (i < N) { rowstart[i] = excl; cursor[i] = excl; }
        __syncthreads();
        if (tid == 1023) s_carry = excl + v;
        __syncthreads();
        v = vnext;
    }
    if (tid == 0) rowstart[N] = E;
}

__global__ void build_kernel(const int* __restrict__ ei, int* __restrict__ cursor,
                             int2* __restrict__ perm, int E)
{
    int e = blockIdx.x * blockDim.x + threadIdx.x;
    if (e >= E) return;
    int s = ei[e];
    int d = ei[E + e];
    int pos = atomicAdd(&cursor[d], 1);
    perm[pos] = make_int2(e, s);
}

// ---------------- layer 0 aggregation: warp per dst, 4-edge batched loads ----------------
__global__ void agg0_kernel(const float* __restrict__ x,
                            const float* __restrict__ ea,
                            const int2* __restrict__ perm,
                            const int* __restrict__ rowstart,
                            float* __restrict__ agg0,
                            int N)
{
    int warp = (blockIdx.x * blockDim.x + threadIdx.x) >> 5;
    int lane = threadIdx.x & 31;
    if (warp >= N) return;

    int beg = rowstart[warp];
    int end = rowstart[warp + 1];

    float4 acc = make_float4(0.f, 0.f, 0.f, 0.f);
    for (int base = beg; base < end; base += 32) {
        int take = min(end - base, 32);
        int2 p = make_int2(0, 0);
        if (lane < take) p = perm[base + lane];

        int j = 0;
        for (; j + 4 <= take; j += 4) {
            int e0 = __shfl_sync(0xFFFFFFFFu, p.x, j + 0);
            int s0 = __shfl_sync(0xFFFFFFFFu, p.y, j + 0);
            int e1 = __shfl_sync(0xFFFFFFFFu, p.x, j + 1);
            int s1 = __shfl_sync(0xFFFFFFFFu, p.y, j + 1);
            int e2 = __shfl_sync(0xFFFFFFFFu, p.x, j + 2);
            int s2 = __shfl_sync(0xFFFFFFFFu, p.y, j + 2);
            int e3 = __shfl_sync(0xFFFFFFFFu, p.x, j + 3);
            int s3 = __shfl_sync(0xFFFFFFFFu, p.y, j + 3);

            float4 ev0 = ldcs4(reinterpret_cast<const float4*>(ea + (long long)e0 * DIN) + lane);
            float4 ev1 = ldcs4(reinterpret_cast<const float4*>(ea + (long long)e1 * DIN) + lane);
            float4 ev2 = ldcs4(reinterpret_cast<const float4*>(ea + (long long)e2 * DIN) + lane);
            float4 ev3 = ldcs4(reinterpret_cast<const float4*>(ea + (long long)e3 * DIN) + lane);
            float4 xv0 = reinterpret_cast<const float4*>(x + (long long)s0 * DIN)[lane];
            float4 xv1 = reinterpret_cast<const float4*>(x + (long long)s1 * DIN)[lane];
            float4 xv2 = reinterpret_cast<const float4*>(x + (long long)s2 * DIN)[lane];
            float4 xv3 = reinterpret_cast<const float4*>(x + (long long)s3 * DIN)[lane];

            acc.x = fmaf(xv0.x, ev0.x, acc.x); acc.y = fmaf(xv0.y, ev0.y, acc.y);
            acc.z = fmaf(xv0.z, ev0.z, acc.z); acc.w = fmaf(xv0.w, ev0.w, acc.w);
            acc.x = fmaf(xv1.x, ev1.x, acc.x); acc.y = fmaf(xv1.y, ev1.y, acc.y);
            acc.z = fmaf(xv1.z, ev1.z, acc.z); acc.w = fmaf(xv1.w, ev1.w, acc.w);
            acc.x = fmaf(xv2.x, ev2.x, acc.x); acc.y = fmaf(xv2.y, ev2.y, acc.y);
            acc.z = fmaf(xv2.z, ev2.z, acc.z); acc.w = fmaf(xv2.w, ev2.w, acc.w);
            acc.x = fmaf(xv3.x, ev3.x, acc.x); acc.y = fmaf(xv3.y, ev3.y, acc.y);
            acc.z = fmaf(xv3.z, ev3.z, acc.z); acc.w = fmaf(xv3.w, ev3.w, acc.w);
        }
        for (; j < take; j++) {
            int e = __shfl_sync(0xFFFFFFFFu, p.x, j);
            int s = __shfl_sync(0xFFFFFFFFu, p.y, j);
            float4 ev = ldcs4(reinterpret_cast<const float4*>(ea + (long long)e * DIN) + lane);
            float4 xv = reinterpret_cast<const float4*>(x + (long long)s * DIN)[lane];
            acc.x = fmaf(xv.x, ev.x, acc.x);
            acc.y = fmaf(xv.y, ev.y, acc.y);
            acc.z = fmaf(xv.z, ev.z, acc.z);
            acc.w = fmaf(xv.w, ev.w, acc.w);
        }
    }
    int deg = end - beg;
    float inv = (deg > 0) ? (1.0f / (float)deg) : 0.f;
    acc.x *= inv; acc.y *= inv; acc.z *= inv; acc.w *= inv;
    reinterpret_cast<float4*>(agg0 + (long long)warp * DIN)[lane] = acc;
}

// ---------------- layer 0 dense: k-chunked register-tiled GEMM ----------------
// Block: 64 nodes x 64 oc, 256 threads, each thread 4x4. k in 4 chunks of 64.
// smem per chunk: W [64][64] 16KB + F [64][64] 16KB = 32KB -> ~7 blocks/SM.
__global__ void layer0_mm_kernel(const float* __restrict__ x,
                                 const float* __restrict__ agg0,
                                 const float* __restrict__ W0,
                                 const float* __restrict__ b0,
                                 float* __restrict__ h,
                                 int N)
{
    __shared__ float sW[64 * HID];   // k-chunk rows x 64 oc
    __shared__ float sF[64 * 64];    // 64 nodes x k-chunk

    int tid = threadIdx.x;
    int to = tid & 15;   // oc quad
    int tn = tid >> 4;   // node quad
    int base = blockIdx.x * 64;

    float c[4][4];
    #pragma unroll
    for (int i = 0; i < 4; i++)
        #pragma unroll
        for (int jj = 0; jj < 4; jj++) c[i][jj] = 0.f;

    for (int kc = 0; kc < 4; kc++) {
        // stage W0 chunk (contiguous 16KB)
        {
            const float4* w4 = reinterpret_cast<const float4*>(W0 + kc * 64 * HID);
            float4* sw4 = reinterpret_cast<float4*>(sW);
            #pragma unroll
            for (int i = 0; i < 4; i++) sw4[tid + 256 * i] = w4[tid + 256 * i];
        }
        // stage F chunk: 64 nodes x 16 float4
        {
            const float* src = (kc < 2) ? x : agg0;
            int koff4 = (kc & 1) * 16;  // float4 offset within 128-ch row
            for (int i = tid; i < 64 * 16; i += 256) {
                int ln = i >> 4;
                int kq = i & 15;
                int node = base + ln;
                float4 v = make_float4(0.f, 0.f, 0.f, 0.f);
                if (node < N)
                    v = reinterpret_cast<const float4*>(src + (long long)node * DIN)[koff4 + kq];
                reinterpret_cast<float4*>(sF + ln * 64)[kq] = v;
            }
        }
        __syncthreads();

        const float* fa0 = sF + (4 * tn + 0) * 64;
        const float* fa1 = sF + (4 * tn + 1) * 64;
        const float* fa2 = sF + (4 * tn + 2) * 64;
        const float* fa3 = sF + (4 * tn + 3) * 64;

        #pragma unroll 8
        for (int k = 0; k < 64; k++) {
            float4 b = reinterpret_cast<const float4*>(sW + k * HID)[to];
            float a0 = fa0[k], a1 = fa1[k], a2 = fa2[k], a3 = fa3[k];
            c[0][0] = fmaf(a0, b.x, c[0][0]); c[0][1] = fmaf(a0, b.y, c[0][1]);
            c[0][2] = fmaf(a0, b.z, c[0][2]); c[0][3] = fmaf(a0, b.w, c[0][3]);
            c[1][0] = fmaf(a1, b.x, c[1][0]); c[1][1] = fmaf(a1, b.y, c[1][1]);
            c[1][2] = fmaf(a1, b.z, c[1][2]); c[1][3] = fmaf(a1, b.w, c[1][3]);
            c[2][0] = fmaf(a2, b.x, c[2][0]); c[2][1] = fmaf(a2, b.y, c[2][1]);
            c[2][2] = fmaf(a2, b.z, c[2][2]); c[2][3] = fmaf(a2, b.w, c[2][3]);
            c[3][0] = fmaf(a3, b.x, c[3][0]); c[3][1] = fmaf(a3, b.y, c[3][1]);
            c[3][2] = fmaf(a3, b.z, c[3][2]); c[3][3] = fmaf(a3, b.w, c[3][3]);
        }
        __syncthreads();
    }

    float4 bias = reinterpret_cast<const float4*>(b0)[to];
    #pragma unroll
    for (int i = 0; i < 4; i++) {
        int node = base + 4 * tn + i;
        if (node < N) {
            float4 o;
            o.x = fmaxf(c[i][0] + bias.x, 0.f);
            o.y = fmaxf(c[i][1] + bias.y, 0.f);
            o.z = fmaxf(c[i][2] + bias.z, 0.f);
            o.w = fmaxf(c[i][3] + bias.w, 0.f);
            reinterpret_cast<float4*>(h + (long long)node * HID)[to] = o;
        }
    }
}

// ---------------- layer 1: project-then-scatter ----------------
__global__ void edgeproj1_kernel(const float* __restrict__ h,
                                 const int* __restrict__ ei,
                                 const float* __restrict__ ea,
                                 const float* __restrict__ W1,
                                 float4* __restrict__ tmp,
                                 int E)
{
    __shared__ float sw[2 * HID]; // W1 rows 64..127
    if (threadIdx.x < 2 * HID) sw[threadIdx.x] = W1[2 * HID + threadIdx.x];
    __syncthreads();

    int warp = (blockIdx.x * blockDim.x + threadIdx.x) >> 5;
    int lane = threadIdx.x & 31;
    if (warp >= E) return;

    int s = ei[warp];
    int d = ei[E + warp];

    float2 hv = reinterpret_cast<const float2*>(h  + (long long)s * HID)[lane];
    float2 ev = reinterpret_cast<const float2*>(ea + (long long)warp * HID)[lane];
    float mx = hv.x * ev.x;
    float my = hv.y * ev.y;

    int k = 2 * lane;
    float a0 = mx * sw[k * 2 + 0] + my * sw[(k + 1) * 2 + 0];
    float a1 = mx * sw[k * 2 + 1] + my * sw[(k + 1) * 2 + 1];

    #pragma unroll
    for (int o = 16; o > 0; o >>= 1) {
        a0 += __shfl_xor_sync(0xFFFFFFFFu, a0, o);
        a1 += __shfl_xor_sync(0xFFFFFFFFu, a1, o);
    }
    if (lane == 0)
        red_add_v4(reinterpret_cast<float*>(tmp + d), a0, a1, 1.0f, 0.f);
}

// ---------------- layer 1 dense ----------------
__global__ void layer1_mm_kernel(const float* __restrict__ h,
                                 const float4* __restrict__ tmp,
                                 const float* __restrict__ W1,
                                 const float* __restrict__ b1,
                                 float* __restrict__ out,
                                 int N)
{
    __shared__ float sW[2 * HID];
    __shared__ float sb[DOUT];
    if (threadIdx.x < 2 * HID) sW[threadIdx.x] = W1[threadIdx.x];
    if (threadIdx.x < DOUT) sb[threadIdx.x] = b1[threadIdx.x];
    __syncthreads();

    int warp = (blockIdx.x * blockDim.x + threadIdx.x) >> 5;
    int lane = threadIdx.x & 31;
    if (warp >= N) return;

    long long rb = (long long)warp * HID;
    float h0 = h[rb + lane];
    float h1 = h[rb + 32 + lane];

    float acc0 = h0 * sW[lane * 2 + 0] + h1 * sW[(32 + lane) * 2 + 0];
    float acc1 = h0 * sW[lane * 2 + 1] + h1 * sW[(32 + lane) * 2 + 1];

    #pragma unroll
    for (int o = 16; o > 0; o >>= 1) {
        acc0 += __shfl_xor_sync(0xFFFFFFFFu, acc0, o);
        acc1 += __shfl_xor_sync(0xFFFFFFFFu, acc1, o);
    }
    if (lane == 0) {
        float4 t = tmp[warp];
        float inv = (t.z > 0.f) ? (1.0f / t.z) : 0.f;
        out[(long long)warp * DOUT + 0] = acc0 + t.x * inv + sb[0];
        out[(long long)warp * DOUT + 1] = acc1 + t.y * inv + sb[1];
    }
}

// ---------------------------------------------------------------------------
extern "C" void kernel_launch(void* const* d_in, const int* in_sizes, int n_in,
                              void* d_out, int out_size)
{
    const float* x   = (const float*)d_in[0];
    const int*   ei  = (const int*)d_in[1];
    const float* ea0 = (const float*)d_in[2];
    const float* ea1 = (const float*)d_in[3];
    const float* W0  = (const float*)d_in[4];
    const float* b0  = (const float*)d_in[5];
    const float* W1  = (const float*)d_in[6];
    const float* b1  = (const float*)d_in[7];
    float* out = (float*)d_out;

    const int N = in_sizes[0] / DIN;
    const int E = in_sizes[1] / 2;

    int *hist_p, *rowstart_p, *cursor_p;
    int2 *perm_p;
    float *agg0_p, *h_p;
    float4 *tmp1_p;
    cudaGetSymbolAddress((void**)&hist_p,     g_hist);
    cudaGetSymbolAddress((void**)&rowstart_p, g_rowstart);
    cudaGetSymbolAddress((void**)&cursor_p,   g_cursor);
    cudaGetSymbolAddress((void**)&perm_p,     g_perm);
    cudaGetSymbolAddress((void**)&agg0_p,     g_agg0);
    cudaGetSymbolAddress((void**)&h_p,        g_h);
    cudaGetSymbolAddress((void**)&tmp1_p,     g_tmp1);

    // launch 0: memset hist
    cudaMemsetAsync(hist_p, 0, (size_t)N * sizeof(int), 0);
    // launch 1: histogram (+ zero tmp1)
    hist_kernel<<<(E + 255) / 256, 256>>>(ei, hist_p, tmp1_p, E, N);
    // launch 2: scan
    scan_kernel<<<1, 1024>>>(hist_p, rowstart_p, cursor_p, N, E);
    // launch 3: perm build
    build_kernel<<<(E + 255) / 256, 256>>>(ei, cursor_p, perm_p, E);
    // launch 4: agg0
    agg0_kernel<<<(N * 32 + 255) / 256, 256>>>(x, ea0, perm_p, rowstart_p, agg0_p, N);
    // launch 5: layer0 GEMM (profiled by ncu -s 5 -c 1)
    layer0_mm_kernel<<<(N + 63) / 64, 256>>>(x, agg0_p, W0, b0, h_p, N);
    // launch 6: layer-1 edge projection + scatter
    edgeproj1_kernel<<<(E * 32 + 255) / 256, 256>>>(h_p, ei, ea1, W1, tmp1_p, E);
    // launch 7: layer-1 dense
    layer1_mm_kernel<<<(N * 32 + 255) / 256, 256>>>(h_p, tmp1_p, W1, b1, out, N);
}

// round 9
// speedup vs baseline: 2.1595x; 1.2662x over previous
#include <cuda_runtime.h>
#include <cuda_bf16.h>
#include <stdint.h>

#define N_NODES 100000
#define E_EDGES 1600000
#define DIN 128
#define HID 64
#define DOUT 2

// Scratch (device globals; no allocation allowed)
__device__ int    g_hist[N_NODES];
__device__ int    g_rowstart[N_NODES + 1];
__device__ int    g_cursor[N_NODES];
__device__ int2   g_perm[E_EDGES];                 // {edge, src} sorted by dst
__device__ float  g_agg0[(size_t)N_NODES * DIN];   // layer-0 MEAN aggregation
__device__ float  g_h[(size_t)N_NODES * HID];      // hidden activations
__device__ float2 g_tmp1[N_NODES];                 // projected layer-1 aggregation {p0,p1}

__device__ __forceinline__ float4 ldcs4(const float4* p) {
    float4 v;
    asm volatile("ld.global.cs.v4.f32 {%0,%1,%2,%3}, [%4];"
                 : "=f"(v.x), "=f"(v.y), "=f"(v.z), "=f"(v.w) : "l"(p));
    return v;
}

__device__ __forceinline__ float2 ldcs2(const float2* p) {
    float2 v;
    asm volatile("ld.global.cs.v2.f32 {%0,%1}, [%2];"
                 : "=f"(v.x), "=f"(v.y) : "l"(p));
    return v;
}

// ---------------- histogram over dst ----------------
__global__ void hist_kernel(const int* __restrict__ ei, int* __restrict__ hist, int E)
{
    int e = blockIdx.x * blockDim.x + threadIdx.x;
    if (e < E) atomicAdd(&hist[ei[E + e]], 1);
}

// ---------------- single-block exclusive scan ----------------
__global__ void scan_kernel(const int* __restrict__ hist,
                            int* __restrict__ rowstart, int* __restrict__ cursor,
                            int N, int E)
{
    __shared__ int warpsum[32];
    __shared__ int s_carry;
    int tid  = threadIdx.x;
    int lane = tid & 31;
    int wid  = tid >> 5;
    if (tid == 0) s_carry = 0;
    __syncthreads();

    int v = (tid < N) ? hist[tid] : 0;
    for (int base = 0; base < N; base += 1024) {
        int inext = base + 1024 + tid;
        int vnext = (inext < N && base + 1024 < N) ? hist[inext] : 0;

        int incl = v;
        #pragma unroll
        for (int off = 1; off < 32; off <<= 1) {
            int t = __shfl_up_sync(0xFFFFFFFFu, incl, off);
            if (lane >= off) incl += t;
        }
        if (lane == 31) warpsum[wid] = incl;
        __syncthreads();
        if (wid == 0) {
            int w = (lane < 32) ? warpsum[lane] : 0;
            int wi = w;
            #pragma unroll
            for (int off = 1; off < 32; off <<= 1) {
                int t = __shfl_up_sync(0xFFFFFFFFu, wi, off);
                if (lane >= off) wi += t;
            }
            warpsum[lane] = wi - w;
        }
        __syncthreads();
        int carry = s_carry;
        int excl = incl - v + warpsum[wid] + carry;
        int i = base + tid;
        if (i < N) { rowstart[i] = excl; cursor[i] = excl; }
        __syncthreads();
        if (tid == 1023) s_carry = excl + v;
        __syncthreads();
        v = vnext;
    }
    if (tid == 0) rowstart[N] = E;
}

__global__ void build_kernel(const int* __restrict__ ei, int* __restrict__ cursor,
                             int2* __restrict__ perm, int E)
{
    int e = blockIdx.x * blockDim.x + threadIdx.x;
    if (e >= E) return;
    int s = ei[e];
    int d = ei[E + e];
    int pos = atomicAdd(&cursor[d], 1);
    perm[pos] = make_int2(e, s);
}

// ---------------- layer 0 aggregation: warp per dst, 4-edge batched loads ----------------
__global__ void agg0_kernel(const float* __restrict__ x,
                            const float* __restrict__ ea,
                            const int2* __restrict__ perm,
                            const int* __restrict__ rowstart,
                            float* __restrict__ agg0,
                            int N)
{
    int warp = (blockIdx.x * blockDim.x + threadIdx.x) >> 5;
    int lane = threadIdx.x & 31;
    if (warp >= N) return;

    int beg = rowstart[warp];
    int end = rowstart[warp + 1];

    float4 acc = make_float4(0.f, 0.f, 0.f, 0.f);
    for (int base = beg; base < end; base += 32) {
        int take = min(end - base, 32);
        int2 p = make_int2(0, 0);
        if (lane < take) p = perm[base + lane];

        int j = 0;
        for (; j + 4 <= take; j += 4) {
            int e0 = __shfl_sync(0xFFFFFFFFu, p.x, j + 0);
            int s0 = __shfl_sync(0xFFFFFFFFu, p.y, j + 0);
            int e1 = __shfl_sync(0xFFFFFFFFu, p.x, j + 1);
            int s1 = __shfl_sync(0xFFFFFFFFu, p.y, j + 1);
            int e2 = __shfl_sync(0xFFFFFFFFu, p.x, j + 2);
            int s2 = __shfl_sync(0xFFFFFFFFu, p.y, j + 2);
            int e3 = __shfl_sync(0xFFFFFFFFu, p.x, j + 3);
            int s3 = __shfl_sync(0xFFFFFFFFu, p.y, j + 3);

            float4 ev0 = ldcs4(reinterpret_cast<const float4*>(ea + (long long)e0 * DIN) + lane);
            float4 ev1 = ldcs4(reinterpret_cast<const float4*>(ea + (long long)e1 * DIN) + lane);
            float4 ev2 = ldcs4(reinterpret_cast<const float4*>(ea + (long long)e2 * DIN) + lane);
            float4 ev3 = ldcs4(reinterpret_cast<const float4*>(ea + (long long)e3 * DIN) + lane);
            float4 xv0 = reinterpret_cast<const float4*>(x + (long long)s0 * DIN)[lane];
            float4 xv1 = reinterpret_cast<const float4*>(x + (long long)s1 * DIN)[lane];
            float4 xv2 = reinterpret_cast<const float4*>(x + (long long)s2 * DIN)[lane];
            float4 xv3 = reinterpret_cast<const float4*>(x + (long long)s3 * DIN)[lane];

            acc.x = fmaf(xv0.x, ev0.x, acc.x); acc.y = fmaf(xv0.y, ev0.y, acc.y);
            acc.z = fmaf(xv0.z, ev0.z, acc.z); acc.w = fmaf(xv0.w, ev0.w, acc.w);
            acc.x = fmaf(xv1.x, ev1.x, acc.x); acc.y = fmaf(xv1.y, ev1.y, acc.y);
            acc.z = fmaf(xv1.z, ev1.z, acc.z); acc.w = fmaf(xv1.w, ev1.w, acc.w);
            acc.x = fmaf(xv2.x, ev2.x, acc.x); acc.y = fmaf(xv2.y, ev2.y, acc.y);
            acc.z = fmaf(xv2.z, ev2.z, acc.z); acc.w = fmaf(xv2.w, ev2.w, acc.w);
            acc.x = fmaf(xv3.x, ev3.x, acc.x); acc.y = fmaf(xv3.y, ev3.y, acc.y);
            acc.z = fmaf(xv3.z, ev3.z, acc.z); acc.w = fmaf(xv3.w, ev3.w, acc.w);
        }
        for (; j < take; j++) {
            int e = __shfl_sync(0xFFFFFFFFu, p.x, j);
            int s = __shfl_sync(0xFFFFFFFFu, p.y, j);
            float4 ev = ldcs4(reinterpret_cast<const float4*>(ea + (long long)e * DIN) + lane);
            float4 xv = reinterpret_cast<const float4*>(x + (long long)s * DIN)[lane];
            acc.x = fmaf(xv.x, ev.x, acc.x);
            acc.y = fmaf(xv.y, ev.y, acc.y);
            acc.z = fmaf(xv.z, ev.z, acc.z);
            acc.w = fmaf(xv.w, ev.w, acc.w);
        }
    }
    int deg = end - beg;
    float inv = (deg > 0) ? (1.0f / (float)deg) : 0.f;
    acc.x *= inv; acc.y *= inv; acc.z *= inv; acc.w *= inv;
    reinterpret_cast<float4*>(agg0 + (long long)warp * DIN)[lane] = acc;
}

// ---------------- layer 0 dense: k-chunked register-tiled GEMM ----------------
__global__ void layer0_mm_kernel(const float* __restrict__ x,
                                 const float* __restrict__ agg0,
                                 const float* __restrict__ W0,
                                 const float* __restrict__ b0,
                                 float* __restrict__ h,
                                 int N)
{
    __shared__ float sW[64 * HID];
    __shared__ float sF[64 * 64];

    int tid = threadIdx.x;
    int to = tid & 15;
    int tn = tid >> 4;
    int base = blockIdx.x * 64;

    float c[4][4];
    #pragma unroll
    for (int i = 0; i < 4; i++)
        #pragma unroll
        for (int jj = 0; jj < 4; jj++) c[i][jj] = 0.f;

    for (int kc = 0; kc < 4; kc++) {
        {
            const float4* w4 = reinterpret_cast<const float4*>(W0 + kc * 64 * HID);
            float4* sw4 = reinterpret_cast<float4*>(sW);
            #pragma unroll
            for (int i = 0; i < 4; i++) sw4[tid + 256 * i] = w4[tid + 256 * i];
        }
        {
            const float* src = (kc < 2) ? x : agg0;
            int koff4 = (kc & 1) * 16;
            for (int i = tid; i < 64 * 16; i += 256) {
                int ln = i >> 4;
                int kq = i & 15;
                int node = base + ln;
                float4 v = make_float4(0.f, 0.f, 0.f, 0.f);
                if (node < N)
                    v = reinterpret_cast<const float4*>(src + (long long)node * DIN)[koff4 + kq];
                reinterpret_cast<float4*>(sF + ln * 64)[kq] = v;
            }
        }
        __syncthreads();

        const float* fa0 = sF + (4 * tn + 0) * 64;
        const float* fa1 = sF + (4 * tn + 1) * 64;
        const float* fa2 = sF + (4 * tn + 2) * 64;
        const float* fa3 = sF + (4 * tn + 3) * 64;

        #pragma unroll 8
        for (int k = 0; k < 64; k++) {
            float4 b = reinterpret_cast<const float4*>(sW + k * HID)[to];
            float a0 = fa0[k], a1 = fa1[k], a2 = fa2[k], a3 = fa3[k];
            c[0][0] = fmaf(a0, b.x, c[0][0]); c[0][1] = fmaf(a0, b.y, c[0][1]);
            c[0][2] = fmaf(a0, b.z, c[0][2]); c[0][3] = fmaf(a0, b.w, c[0][3]);
            c[1][0] = fmaf(a1, b.x, c[1][0]); c[1][1] = fmaf(a1, b.y, c[1][1]);
            c[1][2] = fmaf(a1, b.z, c[1][2]); c[1][3] = fmaf(a1, b.w, c[1][3]);
            c[2][0] = fmaf(a2, b.x, c[2][0]); c[2][1] = fmaf(a2, b.y, c[2][1]);
            c[2][2] = fmaf(a2, b.z, c[2][2]); c[2][3] = fmaf(a2, b.w, c[2][3]);
            c[3][0] = fmaf(a3, b.x, c[3][0]); c[3][1] = fmaf(a3, b.y, c[3][1]);
            c[3][2] = fmaf(a3, b.z, c[3][2]); c[3][3] = fmaf(a3, b.w, c[3][3]);
        }
        __syncthreads();
    }

    float4 bias = reinterpret_cast<const float4*>(b0)[to];
    #pragma unroll
    for (int i = 0; i < 4; i++) {
        int node = base + 4 * tn + i;
        if (node < N) {
            float4 o;
            o.x = fmaxf(c[i][0] + bias.x, 0.f);
            o.y = fmaxf(c[i][1] + bias.y, 0.f);
            o.z = fmaxf(c[i][2] + bias.z, 0.f);
            o.w = fmaxf(c[i][3] + bias.w, 0.f);
            reinterpret_cast<float4*>(h + (long long)node * HID)[to] = o;
        }
    }
}

// ---------------- layer 1: binned aggregation + projection, warp per dst ----------------
// acc (float2/lane) = sum over row edges of h[src]*ea1[e]; then ONE projection
// per dst through W1 rows 64..127, warp-reduce, plain store {p0,p1} (pre-divided).
__global__ void agg1proj_kernel(const float* __restrict__ h,
                                const float* __restrict__ ea,
                                const int2* __restrict__ perm,
                                const int* __restrict__ rowstart,
                                const float* __restrict__ W1,
                                float2* __restrict__ tmp,
                                int N)
{
    __shared__ float sw[2 * HID]; // W1 rows 64..127 (flat 128..255)
    if (threadIdx.x < 2 * HID) sw[threadIdx.x] = W1[2 * HID + threadIdx.x];
    __syncthreads();

    int warp = (blockIdx.x * blockDim.x + threadIdx.x) >> 5;
    int lane = threadIdx.x & 31;
    if (warp >= N) return;

    int beg = rowstart[warp];
    int end = rowstart[warp + 1];

    float2 acc = make_float2(0.f, 0.f);
    for (int base = beg; base < end; base += 32) {
        int take = min(end - base, 32);
        int2 p = make_int2(0, 0);
        if (lane < take) p = perm[base + lane];

        int j = 0;
        for (; j + 4 <= take; j += 4) {
            int e0 = __shfl_sync(0xFFFFFFFFu, p.x, j + 0);
            int s0 = __shfl_sync(0xFFFFFFFFu, p.y, j + 0);
            int e1 = __shfl_sync(0xFFFFFFFFu, p.x, j + 1);
            int s1 = __shfl_sync(0xFFFFFFFFu, p.y, j + 1);
            int e2 = __shfl_sync(0xFFFFFFFFu, p.x, j + 2);
            int s2 = __shfl_sync(0xFFFFFFFFu, p.y, j + 2);
            int e3 = __shfl_sync(0xFFFFFFFFu, p.x, j + 3);
            int s3 = __shfl_sync(0xFFFFFFFFu, p.y, j + 3);

            float2 ev0 = ldcs2(reinterpret_cast<const float2*>(ea + (long long)e0 * HID) + lane);
            float2 ev1 = ldcs2(reinterpret_cast<const float2*>(ea + (long long)e1 * HID) + lane);
            float2 ev2 = ldcs2(reinterpret_cast<const float2*>(ea + (long long)e2 * HID) + lane);
            float2 ev3 = ldcs2(reinterpret_cast<const float2*>(ea + (long long)e3 * HID) + lane);
            float2 hv0 = reinterpret_cast<const float2*>(h + (long long)s0 * HID)[lane];
            float2 hv1 = reinterpret_cast<const float2*>(h + (long long)s1 * HID)[lane];
            float2 hv2 = reinterpret_cast<const float2*>(h + (long long)s2 * HID)[lane];
            float2 hv3 = reinterpret_cast<const float2*>(h + (long long)s3 * HID)[lane];

            acc.x = fmaf(hv0.x, ev0.x, acc.x); acc.y = fmaf(hv0.y, ev0.y, acc.y);
            acc.x = fmaf(hv1.x, ev1.x, acc.x); acc.y = fmaf(hv1.y, ev1.y, acc.y);
            acc.x = fmaf(hv2.x, ev2.x, acc.x); acc.y = fmaf(hv2.y, ev2.y, acc.y);
            acc.x = fmaf(hv3.x, ev3.x, acc.x); acc.y = fmaf(hv3.y, ev3.y, acc.y);
        }
        for (; j < take; j++) {
            int e = __shfl_sync(0xFFFFFFFFu, p.x, j);
            int s = __shfl_sync(0xFFFFFFFFu, p.y, j);
            float2 ev = ldcs2(reinterpret_cast<const float2*>(ea + (long long)e * HID) + lane);
            float2 hv = reinterpret_cast<const float2*>(h + (long long)s * HID)[lane];
            acc.x = fmaf(hv.x, ev.x, acc.x);
            acc.y = fmaf(hv.y, ev.y, acc.y);
        }
    }

    // projection: lane l holds ch {2l, 2l+1}
    float p0 = acc.x * sw[4 * lane + 0] + acc.y * sw[4 * lane + 2];
    float p1 = acc.x * sw[4 * lane + 1] + acc.y * sw[4 * lane + 3];
    #pragma unroll
    for (int o = 16; o > 0; o >>= 1) {
        p0 += __shfl_xor_sync(0xFFFFFFFFu, p0, o);
        p1 += __shfl_xor_sync(0xFFFFFFFFu, p1, o);
    }
    if (lane == 0) {
        int deg = end - beg;
        float inv = (deg > 0) ? (1.0f / (float)deg) : 0.f;
        tmp[warp] = make_float2(p0 * inv, p1 * inv);
    }
}

// ---------------- layer 1 dense: out = h @ W1_top + tmp + b1 ----------------
__global__ void layer1_mm_kernel(const float* __restrict__ h,
                                 const float2* __restrict__ tmp,
                                 const float* __restrict__ W1,
                                 const float* __restrict__ b1,
                                 float* __restrict__ out,
                                 int N)
{
    __shared__ float sW[2 * HID];
    __shared__ float sb[DOUT];
    if (threadIdx.x < 2 * HID) sW[threadIdx.x] = W1[threadIdx.x];
    if (threadIdx.x < DOUT) sb[threadIdx.x] = b1[threadIdx.x];
    __syncthreads();

    int warp = (blockIdx.x * blockDim.x + threadIdx.x) >> 5;
    int lane = threadIdx.x & 31;
    if (warp >= N) return;

    long long rb = (long long)warp * HID;
    float h0 = h[rb + lane];
    float h1 = h[rb + 32 + lane];

    float acc0 = h0 * sW[lane * 2 + 0] + h1 * sW[(32 + lane) * 2 + 0];
    float acc1 = h0 * sW[lane * 2 + 1] + h1 * sW[(32 + lane) * 2 + 1];

    #pragma unroll
    for (int o = 16; o > 0; o >>= 1) {
        acc0 += __shfl_xor_sync(0xFFFFFFFFu, acc0, o);
        acc1 += __shfl_xor_sync(0xFFFFFFFFu, acc1, o);
    }
    if (lane == 0) {
        float2 t = tmp[warp];
        out[(long long)warp * DOUT + 0] = acc0 + t.x + sb[0];
        out[(long long)warp * DOUT + 1] = acc1 + t.y + sb[1];
    }
}

// ---------------------------------------------------------------------------
extern "C" void kernel_launch(void* const* d_in, const int* in_sizes, int n_in,
                              void* d_out, int out_size)
{
    const float* x   = (const float*)d_in[0];
    const int*   ei  = (const int*)d_in[1];
    const float* ea0 = (const float*)d_in[2];
    const float* ea1 = (const float*)d_in[3];
    const float* W0  = (const float*)d_in[4];
    const float* b0  = (const float*)d_in[5];
    const float* W1  = (const float*)d_in[6];
    const float* b1  = (const float*)d_in[7];
    float* out = (float*)d_out;

    const int N = in_sizes[0] / DIN;
    const int E = in_sizes[1] / 2;

    int *hist_p, *rowstart_p, *cursor_p;
    int2 *perm_p;
    float *agg0_p, *h_p;
    float2 *tmp1_p;
    cudaGetSymbolAddress((void**)&hist_p,     g_hist);
    cudaGetSymbolAddress((void**)&rowstart_p, g_rowstart);
    cudaGetSymbolAddress((void**)&cursor_p,   g_cursor);
    cudaGetSymbolAddress((void**)&perm_p,     g_perm);
    cudaGetSymbolAddress((void**)&agg0_p,     g_agg0);
    cudaGetSymbolAddress((void**)&h_p,        g_h);
    cudaGetSymbolAddress((void**)&tmp1_p,     g_tmp1);

    cudaMemsetAsync(hist_p, 0, (size_t)N * sizeof(int), 0);
    hist_kernel<<<(E + 255) / 256, 256>>>(ei, hist_p, E);
    scan_kernel<<<1, 1024>>>(hist_p, rowstart_p, cursor_p, N, E);
    build_kernel<<<(E + 255) / 256, 256>>>(ei, cursor_p, perm_p, E);
    agg0_kernel<<<(N * 32 + 255) / 256, 256>>>(x, ea0, perm_p, rowstart_p, agg0_p, N);
    layer0_mm_kernel<<<(N + 63) / 64, 256>>>(x, agg0_p, W0, b0, h_p, N);
    agg1proj_kernel<<<(N * 32 + 255) / 256, 256>>>(h_p, ea1, perm_p, rowstart_p, W1, tmp1_p, N);
    layer1_mm_kernel<<<(N * 32 + 255) / 256, 256>>>(h_p, tmp1_p, W1, b1, out, N);
}

// round 10
// speedup vs baseline: 2.2341x; 1.0346x over previous
#include <cuda_runtime.h>
#include <cuda_bf16.h>
#include <stdint.h>

#define N_NODES 100000
#define E_EDGES 1600000
#define DIN 128
#define HID 64
#define DOUT 2

// Scratch (device globals; no allocation allowed)
__device__ int    g_hist[N_NODES];
__device__ int    g_rowstart[N_NODES + 1];
__device__ int    g_cursor[N_NODES];
__device__ int2   g_perm[E_EDGES];                 // {edge, src} sorted by dst
__device__ float  g_agg0[(size_t)N_NODES * DIN];   // layer-0 MEAN aggregation
__device__ float  g_h[(size_t)N_NODES * HID];      // hidden activations

__device__ __forceinline__ float4 ldcs4(const float4* p) {
    float4 v;
    asm volatile("ld.global.cs.v4.f32 {%0,%1,%2,%3}, [%4];"
                 : "=f"(v.x), "=f"(v.y), "=f"(v.z), "=f"(v.w) : "l"(p));
    return v;
}

__device__ __forceinline__ float2 ldcs2(const float2* p) {
    float2 v;
    asm volatile("ld.global.cs.v2.f32 {%0,%1}, [%2];"
                 : "=f"(v.x), "=f"(v.y) : "l"(p));
    return v;
}

// ---------------- histogram over dst ----------------
__global__ void hist_kernel(const int* __restrict__ ei, int* __restrict__ hist, int E)
{
    int e = blockIdx.x * blockDim.x + threadIdx.x;
    if (e < E) atomicAdd(&hist[ei[E + e]], 1);
}

// ---------------- single-block exclusive scan ----------------
__global__ void scan_kernel(const int* __restrict__ hist,
                            int* __restrict__ rowstart, int* __restrict__ cursor,
                            int N, int E)
{
    __shared__ int warpsum[32];
    __shared__ int s_carry;
    int tid  = threadIdx.x;
    int lane = tid & 31;
    int wid  = tid >> 5;
    if (tid == 0) s_carry = 0;
    __syncthreads();

    int v = (tid < N) ? hist[tid] : 0;
    for (int base = 0; base < N; base += 1024) {
        int inext = base + 1024 + tid;
        int vnext = (inext < N && base + 1024 < N) ? hist[inext] : 0;

        int incl = v;
        #pragma unroll
        for (int off = 1; off < 32; off <<= 1) {
            int t = __shfl_up_sync(0xFFFFFFFFu, incl, off);
            if (lane >= off) incl += t;
        }
        if (lane == 31) warpsum[wid] = incl;
        __syncthreads();
        if (wid == 0) {
            int w = (lane < 32) ? warpsum[lane] : 0;
            int wi = w;
            #pragma unroll
            for (int off = 1; off < 32; off <<= 1) {
                int t = __shfl_up_sync(0xFFFFFFFFu, wi, off);
                if (lane >= off) wi += t;
            }
            warpsum[lane] = wi - w;
        }
        __syncthreads();
        int carry = s_carry;
        int excl = incl - v + warpsum[wid] + carry;
        int i = base + tid;
        if (i < N) { rowstart[i] = excl; cursor[i] = excl; }
        __syncthreads();
        if (tid == 1023) s_carry = excl + v;
        __syncthreads();
        v = vnext;
    }
    if (tid == 0) rowstart[N] = E;
}

__global__ void build_kernel(const int* __restrict__ ei, int* __restrict__ cursor,
                             int2* __restrict__ perm, int E)
{
    int e = blockIdx.x * blockDim.x + threadIdx.x;
    if (e >= E) return;
    int s = ei[e];
    int d = ei[E + e];
    int pos = atomicAdd(&cursor[d], 1);
    perm[pos] = make_int2(e, s);
}

// ---------------- layer 0 aggregation: warp per dst, 4-edge batched loads ----------------
__global__ void __launch_bounds__(256, 6)
agg0_kernel(const float* __restrict__ x,
            const float* __restrict__ ea,
            const int2* __restrict__ perm,
            const int* __restrict__ rowstart,
            float* __restrict__ agg0,
            int N)
{
    int warp = (blockIdx.x * blockDim.x + threadIdx.x) >> 5;
    int lane = threadIdx.x & 31;
    if (warp >= N) return;

    int beg = rowstart[warp];
    int end = rowstart[warp + 1];

    float4 acc = make_float4(0.f, 0.f, 0.f, 0.f);
    for (int base = beg; base < end; base += 32) {
        int take = min(end - base, 32);
        int2 p = make_int2(0, 0);
        if (lane < take) p = perm[base + lane];

        int j = 0;
        for (; j + 4 <= take; j += 4) {
            int e0 = __shfl_sync(0xFFFFFFFFu, p.x, j + 0);
            int s0 = __shfl_sync(0xFFFFFFFFu, p.y, j + 0);
            int e1 = __shfl_sync(0xFFFFFFFFu, p.x, j + 1);
            int s1 = __shfl_sync(0xFFFFFFFFu, p.y, j + 1);
            int e2 = __shfl_sync(0xFFFFFFFFu, p.x, j + 2);
            int s2 = __shfl_sync(0xFFFFFFFFu, p.y, j + 2);
            int e3 = __shfl_sync(0xFFFFFFFFu, p.x, j + 3);
            int s3 = __shfl_sync(0xFFFFFFFFu, p.y, j + 3);

            float4 ev0 = ldcs4(reinterpret_cast<const float4*>(ea + (long long)e0 * DIN) + lane);
            float4 ev1 = ldcs4(reinterpret_cast<const float4*>(ea + (long long)e1 * DIN) + lane);
            float4 ev2 = ldcs4(reinterpret_cast<const float4*>(ea + (long long)e2 * DIN) + lane);
            float4 ev3 = ldcs4(reinterpret_cast<const float4*>(ea + (long long)e3 * DIN) + lane);
            float4 xv0 = reinterpret_cast<const float4*>(x + (long long)s0 * DIN)[lane];
            float4 xv1 = reinterpret_cast<const float4*>(x + (long long)s1 * DIN)[lane];
            float4 xv2 = reinterpret_cast<const float4*>(x + (long long)s2 * DIN)[lane];
            float4 xv3 = reinterpret_cast<const float4*>(x + (long long)s3 * DIN)[lane];

            acc.x = fmaf(xv0.x, ev0.x, acc.x); acc.y = fmaf(xv0.y, ev0.y, acc.y);
            acc.z = fmaf(xv0.z, ev0.z, acc.z); acc.w = fmaf(xv0.w, ev0.w, acc.w);
            acc.x = fmaf(xv1.x, ev1.x, acc.x); acc.y = fmaf(xv1.y, ev1.y, acc.y);
            acc.z = fmaf(xv1.z, ev1.z, acc.z); acc.w = fmaf(xv1.w, ev1.w, acc.w);
            acc.x = fmaf(xv2.x, ev2.x, acc.x); acc.y = fmaf(xv2.y, ev2.y, acc.y);
            acc.z = fmaf(xv2.z, ev2.z, acc.z); acc.w = fmaf(xv2.w, ev2.w, acc.w);
            acc.x = fmaf(xv3.x, ev3.x, acc.x); acc.y = fmaf(xv3.y, ev3.y, acc.y);
            acc.z = fmaf(xv3.z, ev3.z, acc.z); acc.w = fmaf(xv3.w, ev3.w, acc.w);
        }
        for (; j < take; j++) {
            int e = __shfl_sync(0xFFFFFFFFu, p.x, j);
            int s = __shfl_sync(0xFFFFFFFFu, p.y, j);
            float4 ev = ldcs4(reinterpret_cast<const float4*>(ea + (long long)e * DIN) + lane);
            float4 xv = reinterpret_cast<const float4*>(x + (long long)s * DIN)[lane];
            acc.x = fmaf(xv.x, ev.x, acc.x);
            acc.y = fmaf(xv.y, ev.y, acc.y);
            acc.z = fmaf(xv.z, ev.z, acc.z);
            acc.w = fmaf(xv.w, ev.w, acc.w);
        }
    }
    int deg = end - beg;
    float inv = (deg > 0) ? (1.0f / (float)deg) : 0.f;
    acc.x *= inv; acc.y *= inv; acc.z *= inv; acc.w *= inv;
    reinterpret_cast<float4*>(agg0 + (long long)warp * DIN)[lane] = acc;
}

// ---------------- layer 0 dense: k-chunked register-tiled GEMM ----------------
__global__ void layer0_mm_kernel(const float* __restrict__ x,
                                 const float* __restrict__ agg0,
                                 const float* __restrict__ W0,
                                 const float* __restrict__ b0,
                                 float* __restrict__ h,
                                 int N)
{
    __shared__ float sW[64 * HID];
    __shared__ float sF[64 * 64];

    int tid = threadIdx.x;
    int to = tid & 15;
    int tn = tid >> 4;
    int base = blockIdx.x * 64;

    float c[4][4];
    #pragma unroll
    for (int i = 0; i < 4; i++)
        #pragma unroll
        for (int jj = 0; jj < 4; jj++) c[i][jj] = 0.f;

    for (int kc = 0; kc < 4; kc++) {
        {
            const float4* w4 = reinterpret_cast<const float4*>(W0 + kc * 64 * HID);
            float4* sw4 = reinterpret_cast<float4*>(sW);
            #pragma unroll
            for (int i = 0; i < 4; i++) sw4[tid + 256 * i] = w4[tid + 256 * i];
        }
        {
            const float* src = (kc < 2) ? x : agg0;
            int koff4 = (kc & 1) * 16;
            for (int i = tid; i < 64 * 16; i += 256) {
                int ln = i >> 4;
                int kq = i & 15;
                int node = base + ln;
                float4 v = make_float4(0.f, 0.f, 0.f, 0.f);
                if (node < N)
                    v = reinterpret_cast<const float4*>(src + (long long)node * DIN)[koff4 + kq];
                reinterpret_cast<float4*>(sF + ln * 64)[kq] = v;
            }
        }
        __syncthreads();

        const float* fa0 = sF + (4 * tn + 0) * 64;
        const float* fa1 = sF + (4 * tn + 1) * 64;
        const float* fa2 = sF + (4 * tn + 2) * 64;
        const float* fa3 = sF + (4 * tn + 3) * 64;

        #pragma unroll 8
        for (int k = 0; k < 64; k++) {
            float4 b = reinterpret_cast<const float4*>(sW + k * HID)[to];
            float a0 = fa0[k], a1 = fa1[k], a2 = fa2[k], a3 = fa3[k];
            c[0][0] = fmaf(a0, b.x, c[0][0]); c[0][1] = fmaf(a0, b.y, c[0][1]);
            c[0][2] = fmaf(a0, b.z, c[0][2]); c[0][3] = fmaf(a0, b.w, c[0][3]);
            c[1][0] = fmaf(a1, b.x, c[1][0]); c[1][1] = fmaf(a1, b.y, c[1][1]);
            c[1][2] = fmaf(a1, b.z, c[1][2]); c[1][3] = fmaf(a1, b.w, c[1][3]);
            c[2][0] = fmaf(a2, b.x, c[2][0]); c[2][1] = fmaf(a2, b.y, c[2][1]);
            c[2][2] = fmaf(a2, b.z, c[2][2]); c[2][3] = fmaf(a2, b.w, c[2][3]);
            c[3][0] = fmaf(a3, b.x, c[3][0]); c[3][1] = fmaf(a3, b.y, c[3][1]);
            c[3][2] = fmaf(a3, b.z, c[3][2]); c[3][3] = fmaf(a3, b.w, c[3][3]);
        }
        __syncthreads();
    }

    float4 bias = reinterpret_cast<const float4*>(b0)[to];
    #pragma unroll
    for (int i = 0; i < 4; i++) {
        int node = base + 4 * tn + i;
        if (node < N) {
            float4 o;
            o.x = fmaxf(c[i][0] + bias.x, 0.f);
            o.y = fmaxf(c[i][1] + bias.y, 0.f);
            o.z = fmaxf(c[i][2] + bias.z, 0.f);
            o.w = fmaxf(c[i][3] + bias.w, 0.f);
            reinterpret_cast<float4*>(h + (long long)node * HID)[to] = o;
        }
    }
}

// ---------------- fused layer 1: binned aggregation + projection + self-term + output ----------------
// Warp per dst d:
//   acc = sum_{e in row} h[src(e)] * ea1[e]           (float2/lane)
//   out[d] = (acc @ W1_bot)/deg + h[d] @ W1_top + b1  (one merged warp reduction)
__global__ void agg1_fused_kernel(const float* __restrict__ h,
                                  const float* __restrict__ ea,
                                  const int2* __restrict__ perm,
                                  const int* __restrict__ rowstart,
                                  const float* __restrict__ W1,
                                  const float* __restrict__ b1,
                                  float* __restrict__ out,
                                  int N)
{
    __shared__ float swB[2 * HID]; // W1 rows 64..127 (flat 128..255)
    __shared__ float swT[2 * HID]; // W1 rows 0..63   (flat 0..127)
    __shared__ float sb[DOUT];
    if (threadIdx.x < 2 * HID) {
        swT[threadIdx.x] = W1[threadIdx.x];
        swB[threadIdx.x] = W1[2 * HID + threadIdx.x];
    }
    if (threadIdx.x < DOUT) sb[threadIdx.x] = b1[threadIdx.x];
    __syncthreads();

    int warp = (blockIdx.x * blockDim.x + threadIdx.x) >> 5;
    int lane = threadIdx.x & 31;
    if (warp >= N) return;

    int beg = rowstart[warp];
    int end = rowstart[warp + 1];

    float2 acc = make_float2(0.f, 0.f);
    for (int base = beg; base < end; base += 32) {
        int take = min(end - base, 32);
        int2 p = make_int2(0, 0);
        if (lane < take) p = perm[base + lane];

        int j = 0;
        for (; j + 4 <= take; j += 4) {
            int e0 = __shfl_sync(0xFFFFFFFFu, p.x, j + 0);
            int s0 = __shfl_sync(0xFFFFFFFFu, p.y, j + 0);
            int e1 = __shfl_sync(0xFFFFFFFFu, p.x, j + 1);
            int s1 = __shfl_sync(0xFFFFFFFFu, p.y, j + 1);
            int e2 = __shfl_sync(0xFFFFFFFFu, p.x, j + 2);
            int s2 = __shfl_sync(0xFFFFFFFFu, p.y, j + 2);
            int e3 = __shfl_sync(0xFFFFFFFFu, p.x, j + 3);
            int s3 = __shfl_sync(0xFFFFFFFFu, p.y, j + 3);

            float2 ev0 = ldcs2(reinterpret_cast<const float2*>(ea + (long long)e0 * HID) + lane);
            float2 ev1 = ldcs2(reinterpret_cast<const float2*>(ea + (long long)e1 * HID) + lane);
            float2 ev2 = ldcs2(reinterpret_cast<const float2*>(ea + (long long)e2 * HID) + lane);
            float2 ev3 = ldcs2(reinterpret_cast<const float2*>(ea + (long long)e3 * HID) + lane);
            float2 hv0 = reinterpret_cast<const float2*>(h + (long long)s0 * HID)[lane];
            float2 hv1 = reinterpret_cast<const float2*>(h + (long long)s1 * HID)[lane];
            float2 hv2 = reinterpret_cast<const float2*>(h + (long long)s2 * HID)[lane];
            float2 hv3 = reinterpret_cast<const float2*>(h + (long long)s3 * HID)[lane];

            acc.x = fmaf(hv0.x, ev0.x, acc.x); acc.y = fmaf(hv0.y, ev0.y, acc.y);
            acc.x = fmaf(hv1.x, ev1.x, acc.x); acc.y = fmaf(hv1.y, ev1.y, acc.y);
            acc.x = fmaf(hv2.x, ev2.x, acc.x); acc.y = fmaf(hv2.y, ev2.y, acc.y);
            acc.x = fmaf(hv3.x, ev3.x, acc.x); acc.y = fmaf(hv3.y, ev3.y, acc.y);
        }
        for (; j < take; j++) {
            int e = __shfl_sync(0xFFFFFFFFu, p.x, j);
            int s = __shfl_sync(0xFFFFFFFFu, p.y, j);
            float2 ev = ldcs2(reinterpret_cast<const float2*>(ea + (long long)e * HID) + lane);
            float2 hv = reinterpret_cast<const float2*>(h + (long long)s * HID)[lane];
            acc.x = fmaf(hv.x, ev.x, acc.x);
            acc.y = fmaf(hv.y, ev.y, acc.y);
        }
    }

    int deg = end - beg;
    float inv = (deg > 0) ? (1.0f / (float)deg) : 0.f;

    // self term: lane l holds h[warp] channels {2l, 2l+1}
    float2 hd = reinterpret_cast<const float2*>(h + (long long)warp * HID)[lane];

    // merged per-lane partials: agg part (pre-divided) + self part
    float r0 = (acc.x * swB[4 * lane + 0] + acc.y * swB[4 * lane + 2]) * inv
             +  hd.x * swT[4 * lane + 0] + hd.y * swT[4 * lane + 2];
    float r1 = (acc.x * swB[4 * lane + 1] + acc.y * swB[4 * lane + 3]) * inv
             +  hd.x * swT[4 * lane + 1] + hd.y * swT[4 * lane + 3];

    #pragma unroll
    for (int o = 16; o > 0; o >>= 1) {
        r0 += __shfl_xor_sync(0xFFFFFFFFu, r0, o);
        r1 += __shfl_xor_sync(0xFFFFFFFFu, r1, o);
    }
    if (lane == 0) {
        out[(long long)warp * DOUT + 0] = r0 + sb[0];
        out[(long long)warp * DOUT + 1] = r1 + sb[1];
    }
}

// ---------------------------------------------------------------------------
extern "C" void kernel_launch(void* const* d_in, const int* in_sizes, int n_in,
                              void* d_out, int out_size)
{
    const float* x   = (const float*)d_in[0];
    const int*   ei  = (const int*)d_in[1];
    const float* ea0 = (const float*)d_in[2];
    const float* ea1 = (const float*)d_in[3];
    const float* W0  = (const float*)d_in[4];
    const float* b0  = (const float*)d_in[5];
    const float* W1  = (const float*)d_in[6];
    const float* b1  = (const float*)d_in[7];
    float* out = (float*)d_out;

    const int N = in_sizes[0] / DIN;
    const int E = in_sizes[1] / 2;

    int *hist_p, *rowstart_p, *cursor_p;
    int2 *perm_p;
    float *agg0_p, *h_p;
    cudaGetSymbolAddress((void**)&hist_p,     g_hist);
    cudaGetSymbolAddress((void**)&rowstart_p, g_rowstart);
    cudaGetSymbolAddress((void**)&cursor_p,   g_cursor);
    cudaGetSymbolAddress((void**)&perm_p,     g_perm);
    cudaGetSymbolAddress((void**)&agg0_p,     g_agg0);
    cudaGetSymbolAddress((void**)&h_p,        g_h);

    // launch 0: memset hist
    cudaMemsetAsync(hist_p, 0, (size_t)N * sizeof(int), 0);
    // launch 1: histogram
    hist_kernel<<<(E + 255) / 256, 256>>>(ei, hist_p, E);
    // launch 2: scan
    scan_kernel<<<1, 1024>>>(hist_p, rowstart_p, cursor_p, N, E);
    // launch 3: perm build
    build_kernel<<<(E + 255) / 256, 256>>>(ei, cursor_p, perm_p, E);
    // launch 4: agg0
    agg0_kernel<<<(N * 32 + 255) / 256, 256>>>(x, ea0, perm_p, rowstart_p, agg0_p, N);
    // launch 5: layer0 GEMM (profiled by ncu -s 5 -c 1)
    layer0_mm_kernel<<<(N + 63) / 64, 256>>>(x, agg0_p, W0, b0, h_p, N);
    // launch 6: fused layer-1
    agg1_fused_kernel<<<(N * 32 + 255) / 256, 256>>>(h_p, ea1, perm_p, rowstart_p,
                                                     W1, b1, out, N);
}

// round 11
// speedup vs baseline: 2.3205x; 1.0387x over previous
#include <cuda_runtime.h>
#include <cuda_bf16.h>
#include <stdint.h>

#define N_NODES 100000
#define E_EDGES 1600000
#define DIN 128
#define HID 64
#define DOUT 2

// Scratch (device globals; no allocation allowed)
__device__ int    g_hist[N_NODES];
__device__ int    g_rowstart[N_NODES + 1];
__device__ int    g_cursor[N_NODES];
__device__ int2   g_perm[E_EDGES];                 // {edge, src} sorted by dst
__device__ float  g_agg0[(size_t)N_NODES * DIN];   // layer-0 MEAN aggregation
__device__ float  g_h[(size_t)N_NODES * HID];      // hidden activations

__device__ __forceinline__ float4 ldcs4(const float4* p) {
    float4 v;
    asm volatile("ld.global.cs.v4.f32 {%0,%1,%2,%3}, [%4];"
                 : "=f"(v.x), "=f"(v.y), "=f"(v.z), "=f"(v.w) : "l"(p));
    return v;
}

__device__ __forceinline__ float2 ldcs2(const float2* p) {
    float2 v;
    asm volatile("ld.global.cs.v2.f32 {%0,%1}, [%2];"
                 : "=f"(v.x), "=f"(v.y) : "l"(p));
    return v;
}

// ---------------- histogram over dst ----------------
__global__ void hist_kernel(const int* __restrict__ ei, int* __restrict__ hist, int E)
{
    int e = blockIdx.x * blockDim.x + threadIdx.x;
    if (e < E) atomicAdd(&hist[ei[E + e]], 1);
}

// ---------------- single-block exclusive scan ----------------
__global__ void scan_kernel(const int* __restrict__ hist,
                            int* __restrict__ rowstart, int* __restrict__ cursor,
                            int N, int E)
{
    __shared__ int warpsum[32];
    __shared__ int s_carry;
    int tid  = threadIdx.x;
    int lane = tid & 31;
    int wid  = tid >> 5;
    if (tid == 0) s_carry = 0;
    __syncthreads();

    int v = (tid < N) ? hist[tid] : 0;
    for (int base = 0; base < N; base += 1024) {
        int inext = base + 1024 + tid;
        int vnext = (inext < N && base + 1024 < N) ? hist[inext] : 0;

        int incl = v;
        #pragma unroll
        for (int off = 1; off < 32; off <<= 1) {
            int t = __shfl_up_sync(0xFFFFFFFFu, incl, off);
            if (lane >= off) incl += t;
        }
        if (lane == 31) warpsum[wid] = incl;
        __syncthreads();
        if (wid == 0) {
            int w = (lane < 32) ? warpsum[lane] : 0;
            int wi = w;
            #pragma unroll
            for (int off = 1; off < 32; off <<= 1) {
                int t = __shfl_up_sync(0xFFFFFFFFu, wi, off);
                if (lane >= off) wi += t;
            }
            warpsum[lane] = wi - w;
        }
        __syncthreads();
        int carry = s_carry;
        int excl = incl - v + warpsum[wid] + carry;
        int i = base + tid;
        if (i < N) { rowstart[i] = excl; cursor[i] = excl; }
        __syncthreads();
        if (tid == 1023) s_carry = excl + v;
        __syncthreads();
        v = vnext;
    }
    if (tid == 0) rowstart[N] = E;
}

__global__ void build_kernel(const int* __restrict__ ei, int* __restrict__ cursor,
                             int2* __restrict__ perm, int E)
{
    int e = blockIdx.x * blockDim.x + threadIdx.x;
    if (e >= E) return;
    int s = ei[e];
    int d = ei[E + e];
    int pos = atomicAdd(&cursor[d], 1);
    perm[pos] = make_int2(e, s);
}

// ---------------- layer 0 aggregation: warp per dst, 4-edge batched loads ----------------
__global__ void __launch_bounds__(256, 6)
agg0_kernel(const float* __restrict__ x,
            const float* __restrict__ ea,
            const int2* __restrict__ perm,
            const int* __restrict__ rowstart,
            float* __restrict__ agg0,
            int N)
{
    int warp = (blockIdx.x * blockDim.x + threadIdx.x) >> 5;
    int lane = threadIdx.x & 31;
    if (warp >= N) return;

    int beg = rowstart[warp];
    int end = rowstart[warp + 1];

    float4 acc = make_float4(0.f, 0.f, 0.f, 0.f);
    for (int base = beg; base < end; base += 32) {
        int take = min(end - base, 32);
        int2 p = make_int2(0, 0);
        if (lane < take) p = perm[base + lane];

        int j = 0;
        for (; j + 4 <= take; j += 4) {
            int e0 = __shfl_sync(0xFFFFFFFFu, p.x, j + 0);
            int s0 = __shfl_sync(0xFFFFFFFFu, p.y, j + 0);
            int e1 = __shfl_sync(0xFFFFFFFFu, p.x, j + 1);
            int s1 = __shfl_sync(0xFFFFFFFFu, p.y, j + 1);
            int e2 = __shfl_sync(0xFFFFFFFFu, p.x, j + 2);
            int s2 = __shfl_sync(0xFFFFFFFFu, p.y, j + 2);
            int e3 = __shfl_sync(0xFFFFFFFFu, p.x, j + 3);
            int s3 = __shfl_sync(0xFFFFFFFFu, p.y, j + 3);

            float4 ev0 = ldcs4(reinterpret_cast<const float4*>(ea + (long long)e0 * DIN) + lane);
            float4 ev1 = ldcs4(reinterpret_cast<const float4*>(ea + (long long)e1 * DIN) + lane);
            float4 ev2 = ldcs4(reinterpret_cast<const float4*>(ea + (long long)e2 * DIN) + lane);
            float4 ev3 = ldcs4(reinterpret_cast<const float4*>(ea + (long long)e3 * DIN) + lane);
            float4 xv0 = reinterpret_cast<const float4*>(x + (long long)s0 * DIN)[lane];
            float4 xv1 = reinterpret_cast<const float4*>(x + (long long)s1 * DIN)[lane];
            float4 xv2 = reinterpret_cast<const float4*>(x + (long long)s2 * DIN)[lane];
            float4 xv3 = reinterpret_cast<const float4*>(x + (long long)s3 * DIN)[lane];

            acc.x = fmaf(xv0.x, ev0.x, acc.x); acc.y = fmaf(xv0.y, ev0.y, acc.y);
            acc.z = fmaf(xv0.z, ev0.z, acc.z); acc.w = fmaf(xv0.w, ev0.w, acc.w);
            acc.x = fmaf(xv1.x, ev1.x, acc.x); acc.y = fmaf(xv1.y, ev1.y, acc.y);
            acc.z = fmaf(xv1.z, ev1.z, acc.z); acc.w = fmaf(xv1.w, ev1.w, acc.w);
            acc.x = fmaf(xv2.x, ev2.x, acc.x); acc.y = fmaf(xv2.y, ev2.y, acc.y);
            acc.z = fmaf(xv2.z, ev2.z, acc.z); acc.w = fmaf(xv2.w, ev2.w, acc.w);
            acc.x = fmaf(xv3.x, ev3.x, acc.x); acc.y = fmaf(xv3.y, ev3.y, acc.y);
            acc.z = fmaf(xv3.z, ev3.z, acc.z); acc.w = fmaf(xv3.w, ev3.w, acc.w);
        }
        for (; j < take; j++) {
            int e = __shfl_sync(0xFFFFFFFFu, p.x, j);
            int s = __shfl_sync(0xFFFFFFFFu, p.y, j);
            float4 ev = ldcs4(reinterpret_cast<const float4*>(ea + (long long)e * DIN) + lane);
            float4 xv = reinterpret_cast<const float4*>(x + (long long)s * DIN)[lane];
            acc.x = fmaf(xv.x, ev.x, acc.x);
            acc.y = fmaf(xv.y, ev.y, acc.y);
            acc.z = fmaf(xv.z, ev.z, acc.z);
            acc.w = fmaf(xv.w, ev.w, acc.w);
        }
    }
    int deg = end - beg;
    float inv = (deg > 0) ? (1.0f / (float)deg) : 0.f;
    acc.x *= inv; acc.y *= inv; acc.z *= inv; acc.w *= inv;
    reinterpret_cast<float4*>(agg0 + (long long)warp * DIN)[lane] = acc;
}

// ---------------- layer 0 dense: k-chunked register-tiled GEMM ----------------
__global__ void layer0_mm_kernel(const float* __restrict__ x,
                                 const float* __restrict__ agg0,
                                 const float* __restrict__ W0,
                                 const float* __restrict__ b0,
                                 float* __restrict__ h,
                                 int N)
{
    __shared__ float sW[64 * HID];
    __shared__ float sF[64 * 64];

    int tid = threadIdx.x;
    int to = tid & 15;
    int tn = tid >> 4;
    int base = blockIdx.x * 64;

    float c[4][4];
    #pragma unroll
    for (int i = 0; i < 4; i++)
        #pragma unroll
        for (int jj = 0; jj < 4; jj++) c[i][jj] = 0.f;

    for (int kc = 0; kc < 4; kc++) {
        {
            const float4* w4 = reinterpret_cast<const float4*>(W0 + kc * 64 * HID);
            float4* sw4 = reinterpret_cast<float4*>(sW);
            #pragma unroll
            for (int i = 0; i < 4; i++) sw4[tid + 256 * i] = w4[tid + 256 * i];
        }
        {
            const float* src = (kc < 2) ? x : agg0;
            int koff4 = (kc & 1) * 16;
            for (int i = tid; i < 64 * 16; i += 256) {
                int ln = i >> 4;
                int kq = i & 15;
                int node = base + ln;
                float4 v = make_float4(0.f, 0.f, 0.f, 0.f);
                if (node < N)
                    v = reinterpret_cast<const float4*>(src + (long long)node * DIN)[koff4 + kq];
                reinterpret_cast<float4*>(sF + ln * 64)[kq] = v;
            }
        }
        __syncthreads();

        const float* fa0 = sF + (4 * tn + 0) * 64;
        const float* fa1 = sF + (4 * tn + 1) * 64;
        const float* fa2 = sF + (4 * tn + 2) * 64;
        const float* fa3 = sF + (4 * tn + 3) * 64;

        #pragma unroll 8
        for (int k = 0; k < 64; k++) {
            float4 b = reinterpret_cast<const float4*>(sW + k * HID)[to];
            float a0 = fa0[k], a1 = fa1[k], a2 = fa2[k], a3 = fa3[k];
            c[0][0] = fmaf(a0, b.x, c[0][0]); c[0][1] = fmaf(a0, b.y, c[0][1]);
            c[0][2] = fmaf(a0, b.z, c[0][2]); c[0][3] = fmaf(a0, b.w, c[0][3]);
            c[1][0] = fmaf(a1, b.x, c[1][0]); c[1][1] = fmaf(a1, b.y, c[1][1]);
            c[1][2] = fmaf(a1, b.z, c[1][2]); c[1][3] = fmaf(a1, b.w, c[1][3]);
            c[2][0] = fmaf(a2, b.x, c[2][0]); c[2][1] = fmaf(a2, b.y, c[2][1]);
            c[2][2] = fmaf(a2, b.z, c[2][2]); c[2][3] = fmaf(a2, b.w, c[2][3]);
            c[3][0] = fmaf(a3, b.x, c[3][0]); c[3][1] = fmaf(a3, b.y, c[3][1]);
            c[3][2] = fmaf(a3, b.z, c[3][2]); c[3][3] = fmaf(a3, b.w, c[3][3]);
        }
        __syncthreads();
    }

    float4 bias = reinterpret_cast<const float4*>(b0)[to];
    #pragma unroll
    for (int i = 0; i < 4; i++) {
        int node = base + 4 * tn + i;
        if (node < N) {
            float4 o;
            o.x = fmaxf(c[i][0] + bias.x, 0.f);
            o.y = fmaxf(c[i][1] + bias.y, 0.f);
            o.z = fmaxf(c[i][2] + bias.z, 0.f);
            o.w = fmaxf(c[i][3] + bias.w, 0.f);
            reinterpret_cast<float4*>(h + (long long)node * HID)[to] = o;
        }
    }
}

// ---------------- fused layer 1: binned aggregation + projection + self-term + output ----------------
// Warp per dst d, 8-edge batched loads (16 independent 8B loads in flight):
//   acc = sum_{e in row} h[src(e)] * ea1[e]           (float2/lane)
//   out[d] = (acc @ W1_bot)/deg + h[d] @ W1_top + b1  (one merged warp reduction)
__global__ void __launch_bounds__(256, 6)
agg1_fused_kernel(const float* __restrict__ h,
                  const float* __restrict__ ea,
                  const int2* __restrict__ perm,
                  const int* __restrict__ rowstart,
                  const float* __restrict__ W1,
                  const float* __restrict__ b1,
                  float* __restrict__ out,
                  int N)
{
    __shared__ float swB[2 * HID]; // W1 rows 64..127 (flat 128..255)
    __shared__ float swT[2 * HID]; // W1 rows 0..63   (flat 0..127)
    __shared__ float sb[DOUT];
    if (threadIdx.x < 2 * HID) {
        swT[threadIdx.x] = W1[threadIdx.x];
        swB[threadIdx.x] = W1[2 * HID + threadIdx.x];
    }
    if (threadIdx.x < DOUT) sb[threadIdx.x] = b1[threadIdx.x];
    __syncthreads();

    int warp = (blockIdx.x * blockDim.x + threadIdx.x) >> 5;
    int lane = threadIdx.x & 31;
    if (warp >= N) return;

    int beg = rowstart[warp];
    int end = rowstart[warp + 1];

    float2 acc = make_float2(0.f, 0.f);
    for (int base = beg; base < end; base += 32) {
        int take = min(end - base, 32);
        int2 p = make_int2(0, 0);
        if (lane < take) p = perm[base + lane];

        int j = 0;
        for (; j + 8 <= take; j += 8) {
            int e0 = __shfl_sync(0xFFFFFFFFu, p.x, j + 0);
            int s0 = __shfl_sync(0xFFFFFFFFu, p.y, j + 0);
            int e1 = __shfl_sync(0xFFFFFFFFu, p.x, j + 1);
            int s1 = __shfl_sync(0xFFFFFFFFu, p.y, j + 1);
            int e2 = __shfl_sync(0xFFFFFFFFu, p.x, j + 2);
            int s2 = __shfl_sync(0xFFFFFFFFu, p.y, j + 2);
            int e3 = __shfl_sync(0xFFFFFFFFu, p.x, j + 3);
            int s3 = __shfl_sync(0xFFFFFFFFu, p.y, j + 3);
            int e4 = __shfl_sync(0xFFFFFFFFu, p.x, j + 4);
            int s4 = __shfl_sync(0xFFFFFFFFu, p.y, j + 4);
            int e5 = __shfl_sync(0xFFFFFFFFu, p.x, j + 5);
            int s5 = __shfl_sync(0xFFFFFFFFu, p.y, j + 5);
            int e6 = __shfl_sync(0xFFFFFFFFu, p.x, j + 6);
            int s6 = __shfl_sync(0xFFFFFFFFu, p.y, j + 6);
            int e7 = __shfl_sync(0xFFFFFFFFu, p.x, j + 7);
            int s7 = __shfl_sync(0xFFFFFFFFu, p.y, j + 7);

            float2 ev0 = ldcs2(reinterpret_cast<const float2*>(ea + (long long)e0 * HID) + lane);
            float2 ev1 = ldcs2(reinterpret_cast<const float2*>(ea + (long long)e1 * HID) + lane);
            float2 ev2 = ldcs2(reinterpret_cast<const float2*>(ea + (long long)e2 * HID) + lane);
            float2 ev3 = ldcs2(reinterpret_cast<const float2*>(ea + (long long)e3 * HID) + lane);
            float2 ev4 = ldcs2(reinterpret_cast<const float2*>(ea + (long long)e4 * HID) + lane);
            float2 ev5 = ldcs2(reinterpret_cast<const float2*>(ea + (long long)e5 * HID) + lane);
            float2 ev6 = ldcs2(reinterpret_cast<const float2*>(ea + (long long)e6 * HID) + lane);
            float2 ev7 = ldcs2(reinterpret_cast<const float2*>(ea + (long long)e7 * HID) + lane);
            float2 hv0 = reinterpret_cast<const float2*>(h + (long long)s0 * HID)[lane];
            float2 hv1 = reinterpret_cast<const float2*>(h + (long long)s1 * HID)[lane];
            float2 hv2 = reinterpret_cast<const float2*>(h + (long long)s2 * HID)[lane];
            float2 hv3 = reinterpret_cast<const float2*>(h + (long long)s3 * HID)[lane];
            float2 hv4 = reinterpret_cast<const float2*>(h + (long long)s4 * HID)[lane];
            float2 hv5 = reinterpret_cast<const float2*>(h + (long long)s5 * HID)[lane];
            float2 hv6 = reinterpret_cast<const float2*>(h + (long long)s6 * HID)[lane];
            float2 hv7 = reinterpret_cast<const float2*>(h + (long long)s7 * HID)[lane];

            acc.x = fmaf(hv0.x, ev0.x, acc.x); acc.y = fmaf(hv0.y, ev0.y, acc.y);
            acc.x = fmaf(hv1.x, ev1.x, acc.x); acc.y = fmaf(hv1.y, ev1.y, acc.y);
            acc.x = fmaf(hv2.x, ev2.x, acc.x); acc.y = fmaf(hv2.y, ev2.y, acc.y);
            acc.x = fmaf(hv3.x, ev3.x, acc.x); acc.y = fmaf(hv3.y, ev3.y, acc.y);
            acc.x = fmaf(hv4.x, ev4.x, acc.x); acc.y = fmaf(hv4.y, ev4.y, acc.y);
            acc.x = fmaf(hv5.x, ev5.x, acc.x); acc.y = fmaf(hv5.y, ev5.y, acc.y);
            acc.x = fmaf(hv6.x, ev6.x, acc.x); acc.y = fmaf(hv6.y, ev6.y, acc.y);
            acc.x = fmaf(hv7.x, ev7.x, acc.x); acc.y = fmaf(hv7.y, ev7.y, acc.y);
        }
        for (; j < take; j++) {
            int e = __shfl_sync(0xFFFFFFFFu, p.x, j);
            int s = __shfl_sync(0xFFFFFFFFu, p.y, j);
            float2 ev = ldcs2(reinterpret_cast<const float2*>(ea + (long long)e * HID) + lane);
            float2 hv = reinterpret_cast<const float2*>(h + (long long)s * HID)[lane];
            acc.x = fmaf(hv.x, ev.x, acc.x);
            acc.y = fmaf(hv.y, ev.y, acc.y);
        }
    }

    int deg = end - beg;
    float inv = (deg > 0) ? (1.0f / (float)deg) : 0.f;

    // self term: lane l holds h[warp] channels {2l, 2l+1}
    float2 hd = reinterpret_cast<const float2*>(h + (long long)warp * HID)[lane];

    float r0 = (acc.x * swB[4 * lane + 0] + acc.y * swB[4 * lane + 2]) * inv
             +  hd.x * swT[4 * lane + 0] + hd.y * swT[4 * lane + 2];
    float r1 = (acc.x * swB[4 * lane + 1] + acc.y * swB[4 * lane + 3]) * inv
             +  hd.x * swT[4 * lane + 1] + hd.y * swT[4 * lane + 3];

    #pragma unroll
    for (int o = 16; o > 0; o >>= 1) {
        r0 += __shfl_xor_sync(0xFFFFFFFFu, r0, o);
        r1 += __shfl_xor_sync(0xFFFFFFFFu, r1, o);
    }
    if (lane == 0) {
        out[(long long)warp * DOUT + 0] = r0 + sb[0];
        out[(long long)warp * DOUT + 1] = r1 + sb[1];
    }
}

// ---------------------------------------------------------------------------
extern "C" void kernel_launch(void* const* d_in, const int* in_sizes, int n_in,
                              void* d_out, int out_size)
{
    const float* x   = (const float*)d_in[0];
    const int*   ei  = (const int*)d_in[1];
    const float* ea0 = (const float*)d_in[2];
    const float* ea1 = (const float*)d_in[3];
    const float* W0  = (const float*)d_in[4];
    const float* b0  = (const float*)d_in[5];
    const float* W1  = (const float*)d_in[6];
    const float* b1  = (const float*)d_in[7];
    float* out = (float*)d_out;

    const int N = in_sizes[0] / DIN;
    const int E = in_sizes[1] / 2;

    int *hist_p, *rowstart_p, *cursor_p;
    int2 *perm_p;
    float *agg0_p, *h_p;
    cudaGetSymbolAddress((void**)&hist_p,     g_hist);
    cudaGetSymbolAddress((void**)&rowstart_p, g_rowstart);
    cudaGetSymbolAddress((void**)&cursor_p,   g_cursor);
    cudaGetSymbolAddress((void**)&perm_p,     g_perm);
    cudaGetSymbolAddress((void**)&agg0_p,     g_agg0);
    cudaGetSymbolAddress((void**)&h_p,        g_h);

    cudaMemsetAsync(hist_p, 0, (size_t)N * sizeof(int), 0);
    hist_kernel<<<(E + 255) / 256, 256>>>(ei, hist_p, E);
    scan_kernel<<<1, 1024>>>(hist_p, rowstart_p, cursor_p, N, E);
    build_kernel<<<(E + 255) / 256, 256>>>(ei, cursor_p, perm_p, E);
    agg0_kernel<<<(N * 32 + 255) / 256, 256>>>(x, ea0, perm_p, rowstart_p, agg0_p, N);
    layer0_mm_kernel<<<(N + 63) / 64, 256>>>(x, agg0_p, W0, b0, h_p, N);
    agg1_fused_kernel<<<(N * 32 + 255) / 256, 256>>>(h_p, ea1, perm_p, rowstart_p,
                                                     W1, b1, out, N);
}

// round 12
// speedup vs baseline: 2.3594x; 1.0168x over previous
#include <cuda_runtime.h>
#include <cuda_bf16.h>
#include <stdint.h>

#define N_NODES 100000
#define E_EDGES 1600000
#define DIN 128
#define HID 64
#define DOUT 2

// Scratch (device globals; no allocation allowed)
__device__ int    g_hist[N_NODES];
__device__ int    g_rowstart[N_NODES + 1];
__device__ int    g_cursor[N_NODES];
__device__ int2   g_perm[E_EDGES];                 // {edge, src} sorted by dst
__device__ float  g_agg0[(size_t)N_NODES * DIN];   // layer-0 MEAN aggregation
__device__ float  g_h[(size_t)N_NODES * HID];      // hidden activations

__device__ __forceinline__ float4 ldcs4(const float4* p) {
    float4 v;
    asm volatile("ld.global.cs.v4.f32 {%0,%1,%2,%3}, [%4];"
                 : "=f"(v.x), "=f"(v.y), "=f"(v.z), "=f"(v.w) : "l"(p));
    return v;
}

// ---------------- histogram over dst ----------------
__global__ void hist_kernel(const int* __restrict__ ei, int* __restrict__ hist, int E)
{
    int e = blockIdx.x * blockDim.x + threadIdx.x;
    if (e < E) atomicAdd(&hist[ei[E + e]], 1);
}

// ---------------- single-block exclusive scan ----------------
__global__ void scan_kernel(const int* __restrict__ hist,
                            int* __restrict__ rowstart, int* __restrict__ cursor,
                            int N, int E)
{
    __shared__ int warpsum[32];
    __shared__ int s_carry;
    int tid  = threadIdx.x;
    int lane = tid & 31;
    int wid  = tid >> 5;
    if (tid == 0) s_carry = 0;
    __syncthreads();

    int v = (tid < N) ? hist[tid] : 0;
    for (int base = 0; base < N; base += 1024) {
        int inext = base + 1024 + tid;
        int vnext = (inext < N && base + 1024 < N) ? hist[inext] : 0;

        int incl = v;
        #pragma unroll
        for (int off = 1; off < 32; off <<= 1) {
            int t = __shfl_up_sync(0xFFFFFFFFu, incl, off);
            if (lane >= off) incl += t;
        }
        if (lane == 31) warpsum[wid] = incl;
        __syncthreads();
        if (wid == 0) {
            int w = (lane < 32) ? warpsum[lane] : 0;
            int wi = w;
            #pragma unroll
            for (int off = 1; off < 32; off <<= 1) {
                int t = __shfl_up_sync(0xFFFFFFFFu, wi, off);
                if (lane >= off) wi += t;
            }
            warpsum[lane] = wi - w;
        }
        __syncthreads();
        int carry = s_carry;
        int excl = incl - v + warpsum[wid] + carry;
        int i = base + tid;
        if (i < N) { rowstart[i] = excl; cursor[i] = excl; }
        __syncthreads();
        if (tid == 1023) s_carry = excl + v;
        __syncthreads();
        v = vnext;
    }
    if (tid == 0) rowstart[N] = E;
}

__global__ void build_kernel(const int* __restrict__ ei, int* __restrict__ cursor,
                             int2* __restrict__ perm, int E)
{
    int e = blockIdx.x * blockDim.x + threadIdx.x;
    if (e >= E) return;
    int s = ei[e];
    int d = ei[E + e];
    int pos = atomicAdd(&cursor[d], 1);
    perm[pos] = make_int2(e, s);
}

// ---------------- layer 0 aggregation: warp per dst, 4-edge batched loads ----------------
__global__ void __launch_bounds__(256, 6)
agg0_kernel(const float* __restrict__ x,
            const float* __restrict__ ea,
            const int2* __restrict__ perm,
            const int* __restrict__ rowstart,
            float* __restrict__ agg0,
            int N)
{
    int warp = (blockIdx.x * blockDim.x + threadIdx.x) >> 5;
    int lane = threadIdx.x & 31;
    if (warp >= N) return;

    int beg = rowstart[warp];
    int end = rowstart[warp + 1];

    float4 acc = make_float4(0.f, 0.f, 0.f, 0.f);
    for (int base = beg; base < end; base += 32) {
        int take = min(end - base, 32);
        int2 p = make_int2(0, 0);
        if (lane < take) p = perm[base + lane];

        int j = 0;
        for (; j + 4 <= take; j += 4) {
            int e0 = __shfl_sync(0xFFFFFFFFu, p.x, j + 0);
            int s0 = __shfl_sync(0xFFFFFFFFu, p.y, j + 0);
            int e1 = __shfl_sync(0xFFFFFFFFu, p.x, j + 1);
            int s1 = __shfl_sync(0xFFFFFFFFu, p.y, j + 1);
            int e2 = __shfl_sync(0xFFFFFFFFu, p.x, j + 2);
            int s2 = __shfl_sync(0xFFFFFFFFu, p.y, j + 2);
            int e3 = __shfl_sync(0xFFFFFFFFu, p.x, j + 3);
            int s3 = __shfl_sync(0xFFFFFFFFu, p.y, j + 3);

            float4 ev0 = ldcs4(reinterpret_cast<const float4*>(ea + (long long)e0 * DIN) + lane);
            float4 ev1 = ldcs4(reinterpret_cast<const float4*>(ea + (long long)e1 * DIN) + lane);
            float4 ev2 = ldcs4(reinterpret_cast<const float4*>(ea + (long long)e2 * DIN) + lane);
            float4 ev3 = ldcs4(reinterpret_cast<const float4*>(ea + (long long)e3 * DIN) + lane);
            float4 xv0 = reinterpret_cast<const float4*>(x + (long long)s0 * DIN)[lane];
            float4 xv1 = reinterpret_cast<const float4*>(x + (long long)s1 * DIN)[lane];
            float4 xv2 = reinterpret_cast<const float4*>(x + (long long)s2 * DIN)[lane];
            float4 xv3 = reinterpret_cast<const float4*>(x + (long long)s3 * DIN)[lane];

            acc.x = fmaf(xv0.x, ev0.x, acc.x); acc.y = fmaf(xv0.y, ev0.y, acc.y);
            acc.z = fmaf(xv0.z, ev0.z, acc.z); acc.w = fmaf(xv0.w, ev0.w, acc.w);
            acc.x = fmaf(xv1.x, ev1.x, acc.x); acc.y = fmaf(xv1.y, ev1.y, acc.y);
            acc.z = fmaf(xv1.z, ev1.z, acc.z); acc.w = fmaf(xv1.w, ev1.w, acc.w);
            acc.x = fmaf(xv2.x, ev2.x, acc.x); acc.y = fmaf(xv2.y, ev2.y, acc.y);
            acc.z = fmaf(xv2.z, ev2.z, acc.z); acc.w = fmaf(xv2.w, ev2.w, acc.w);
            acc.x = fmaf(xv3.x, ev3.x, acc.x); acc.y = fmaf(xv3.y, ev3.y, acc.y);
            acc.z = fmaf(xv3.z, ev3.z, acc.z); acc.w = fmaf(xv3.w, ev3.w, acc.w);
        }
        for (; j < take; j++) {
            int e = __shfl_sync(0xFFFFFFFFu, p.x, j);
            int s = __shfl_sync(0xFFFFFFFFu, p.y, j);
            float4 ev = ldcs4(reinterpret_cast<const float4*>(ea + (long long)e * DIN) + lane);
            float4 xv = reinterpret_cast<const float4*>(x + (long long)s * DIN)[lane];
            acc.x = fmaf(xv.x, ev.x, acc.x);
            acc.y = fmaf(xv.y, ev.y, acc.y);
            acc.z = fmaf(xv.z, ev.z, acc.z);
            acc.w = fmaf(xv.w, ev.w, acc.w);
        }
    }
    int deg = end - beg;
    float inv = (deg > 0) ? (1.0f / (float)deg) : 0.f;
    acc.x *= inv; acc.y *= inv; acc.z *= inv; acc.w *= inv;
    reinterpret_cast<float4*>(agg0 + (long long)warp * DIN)[lane] = acc;
}

// ---------------- layer 0 dense: k-chunked register-tiled GEMM ----------------
__global__ void layer0_mm_kernel(const float* __restrict__ x,
                                 const float* __restrict__ agg0,
                                 const float* __restrict__ W0,
                                 const float* __restrict__ b0,
                                 float* __restrict__ h,
                                 int N)
{
    __shared__ float sW[64 * HID];
    __shared__ float sF[64 * 64];

    int tid = threadIdx.x;
    int to = tid & 15;
    int tn = tid >> 4;
    int base = blockIdx.x * 64;

    float c[4][4];
    #pragma unroll
    for (int i = 0; i < 4; i++)
        #pragma unroll
        for (int jj = 0; jj < 4; jj++) c[i][jj] = 0.f;

    for (int kc = 0; kc < 4; kc++) {
        {
            const float4* w4 = reinterpret_cast<const float4*>(W0 + kc * 64 * HID);
            float4* sw4 = reinterpret_cast<float4*>(sW);
            #pragma unroll
            for (int i = 0; i < 4; i++) sw4[tid + 256 * i] = w4[tid + 256 * i];
        }
        {
            const float* src = (kc < 2) ? x : agg0;
            int koff4 = (kc & 1) * 16;
            for (int i = tid; i < 64 * 16; i += 256) {
                int ln = i >> 4;
                int kq = i & 15;
                int node = base + ln;
                float4 v = make_float4(0.f, 0.f, 0.f, 0.f);
                if (node < N)
                    v = reinterpret_cast<const float4*>(src + (long long)node * DIN)[koff4 + kq];
                reinterpret_cast<float4*>(sF + ln * 64)[kq] = v;
            }
        }
        __syncthreads();

        const float* fa0 = sF + (4 * tn + 0) * 64;
        const float* fa1 = sF + (4 * tn + 1) * 64;
        const float* fa2 = sF + (4 * tn + 2) * 64;
        const float* fa3 = sF + (4 * tn + 3) * 64;

        #pragma unroll 8
        for (int k = 0; k < 64; k++) {
            float4 b = reinterpret_cast<const float4*>(sW + k * HID)[to];
            float a0 = fa0[k], a1 = fa1[k], a2 = fa2[k], a3 = fa3[k];
            c[0][0] = fmaf(a0, b.x, c[0][0]); c[0][1] = fmaf(a0, b.y, c[0][1]);
            c[0][2] = fmaf(a0, b.z, c[0][2]); c[0][3] = fmaf(a0, b.w, c[0][3]);
            c[1][0] = fmaf(a1, b.x, c[1][0]); c[1][1] = fmaf(a1, b.y, c[1][1]);
            c[1][2] = fmaf(a1, b.z, c[1][2]); c[1][3] = fmaf(a1, b.w, c[1][3]);
            c[2][0] = fmaf(a2, b.x, c[2][0]); c[2][1] = fmaf(a2, b.y, c[2][1]);
            c[2][2] = fmaf(a2, b.z, c[2][2]); c[2][3] = fmaf(a2, b.w, c[2][3]);
            c[3][0] = fmaf(a3, b.x, c[3][0]); c[3][1] = fmaf(a3, b.y, c[3][1]);
            c[3][2] = fmaf(a3, b.z, c[3][2]); c[3][3] = fmaf(a3, b.w, c[3][3]);
        }
        __syncthreads();
    }

    float4 bias = reinterpret_cast<const float4*>(b0)[to];
    #pragma unroll
    for (int i = 0; i < 4; i++) {
        int node = base + 4 * tn + i;
        if (node < N) {
            float4 o;
            o.x = fmaxf(c[i][0] + bias.x, 0.f);
            o.y = fmaxf(c[i][1] + bias.y, 0.f);
            o.z = fmaxf(c[i][2] + bias.z, 0.f);
            o.w = fmaxf(c[i][3] + bias.w, 0.f);
            reinterpret_cast<float4*>(h + (long long)node * HID)[to] = o;
        }
    }
}

// ---------------- fused layer 1: half-warp float4, padded batches ----------------
// Warp per dst d. lane = 16*half + sub; lane covers channels 4*sub..4*sub+3.
// Each 8-edge iteration: half 0 does edges j..j+3, half 1 does j+4..j+7
// (clamped+zeroed past take). acc combined across halves by shfl_xor(16).
// out[d] = (acc @ W1_bot)/deg + h[d] @ W1_top + b1.
__global__ void __launch_bounds__(256, 5)
agg1_fused_kernel(const float* __restrict__ h,
                  const float* __restrict__ ea,
                  const int2* __restrict__ perm,
                  const int* __restrict__ rowstart,
                  const float* __restrict__ W1,
                  const float* __restrict__ b1,
                  float* __restrict__ out,
                  int N)
{
    __shared__ float swB[2 * HID]; // W1 rows 64..127 (flat 128..255)
    __shared__ float swT[2 * HID]; // W1 rows 0..63   (flat 0..127)
    __shared__ float sb[DOUT];
    if (threadIdx.x < 2 * HID) {
        swT[threadIdx.x] = W1[threadIdx.x];
        swB[threadIdx.x] = W1[2 * HID + threadIdx.x];
    }
    if (threadIdx.x < DOUT) sb[threadIdx.x] = b1[threadIdx.x];
    __syncthreads();

    int warp = (blockIdx.x * blockDim.x + threadIdx.x) >> 5;
    int lane = threadIdx.x & 31;
    int half = lane >> 4;
    int sub  = lane & 15;
    if (warp >= N) return;

    int beg = rowstart[warp];
    int end = rowstart[warp + 1];

    float4 acc = make_float4(0.f, 0.f, 0.f, 0.f);
    for (int base = beg; base < end; base += 32) {
        int take = min(end - base, 32);
        int2 p = make_int2(0, 0);
        if (lane < take) p = perm[base + lane];

        for (int j = 0; j < take; j += 8) {
            int i0 = j + 4 * half;
            int tk1 = take - 1;
            int si0 = min(i0 + 0, tk1), si1 = min(i0 + 1, tk1);
            int si2 = min(i0 + 2, tk1), si3 = min(i0 + 3, tk1);
            bool v0 = (i0 + 0) < take, v1 = (i0 + 1) < take;
            bool v2 = (i0 + 2) < take, v3 = (i0 + 3) < take;

            int e0 = __shfl_sync(0xFFFFFFFFu, p.x, si0);
            int s0 = __shfl_sync(0xFFFFFFFFu, p.y, si0);
            int e1 = __shfl_sync(0xFFFFFFFFu, p.x, si1);
            int s1 = __shfl_sync(0xFFFFFFFFu, p.y, si1);
            int e2 = __shfl_sync(0xFFFFFFFFu, p.x, si2);
            int s2 = __shfl_sync(0xFFFFFFFFu, p.y, si2);
            int e3 = __shfl_sync(0xFFFFFFFFu, p.x, si3);
            int s3 = __shfl_sync(0xFFFFFFFFu, p.y, si3);

            float4 ev0 = ldcs4(reinterpret_cast<const float4*>(ea + (long long)e0 * HID) + sub);
            float4 ev1 = ldcs4(reinterpret_cast<const float4*>(ea + (long long)e1 * HID) + sub);
            float4 ev2 = ldcs4(reinterpret_cast<const float4*>(ea + (long long)e2 * HID) + sub);
            float4 ev3 = ldcs4(reinterpret_cast<const float4*>(ea + (long long)e3 * HID) + sub);
            float4 hv0 = reinterpret_cast<const float4*>(h + (long long)s0 * HID)[sub];
            float4 hv1 = reinterpret_cast<const float4*>(h + (long long)s1 * HID)[sub];
            float4 hv2 = reinterpret_cast<const float4*>(h + (long long)s2 * HID)[sub];
            float4 hv3 = reinterpret_cast<const float4*>(h + (long long)s3 * HID)[sub];

            if (!v0) hv0 = make_float4(0.f, 0.f, 0.f, 0.f);
            if (!v1) hv1 = make_float4(0.f, 0.f, 0.f, 0.f);
            if (!v2) hv2 = make_float4(0.f, 0.f, 0.f, 0.f);
            if (!v3) hv3 = make_float4(0.f, 0.f, 0.f, 0.f);

            acc.x = fmaf(hv0.x, ev0.x, acc.x); acc.y = fmaf(hv0.y, ev0.y, acc.y);
            acc.z = fmaf(hv0.z, ev0.z, acc.z); acc.w = fmaf(hv0.w, ev0.w, acc.w);
            acc.x = fmaf(hv1.x, ev1.x, acc.x); acc.y = fmaf(hv1.y, ev1.y, acc.y);
            acc.z = fmaf(hv1.z, ev1.z, acc.z); acc.w = fmaf(hv1.w, ev1.w, acc.w);
            acc.x = fmaf(hv2.x, ev2.x, acc.x); acc.y = fmaf(hv2.y, ev2.y, acc.y);
            acc.z = fmaf(hv2.z, ev2.z, acc.z); acc.w = fmaf(hv2.w, ev2.w, acc.w);
            acc.x = fmaf(hv3.x, ev3.x, acc.x); acc.y = fmaf(hv3.y, ev3.y, acc.y);
            acc.z = fmaf(hv3.z, ev3.z, acc.z); acc.w = fmaf(hv3.w, ev3.w, acc.w);
        }
    }

    // combine the two half-warps' partial sums
    acc.x += __shfl_xor_sync(0xFFFFFFFFu, acc.x, 16);
    acc.y += __shfl_xor_sync(0xFFFFFFFFu, acc.y, 16);
    acc.z += __shfl_xor_sync(0xFFFFFFFFu, acc.z, 16);
    acc.w += __shfl_xor_sync(0xFFFFFFFFu, acc.w, 16);

    int deg = end - beg;
    float inv = (deg > 0) ? (1.0f / (float)deg) : 0.f;

    // self term: lane covers h[warp] channels 4*sub..4*sub+3
    float4 hd = reinterpret_cast<const float4*>(h + (long long)warp * HID)[sub];

    int c0 = 4 * sub;
    float r0 = inv * (acc.x * swB[(c0 + 0) * 2 + 0] + acc.y * swB[(c0 + 1) * 2 + 0]
                    + acc.z * swB[(c0 + 2) * 2 + 0] + acc.w * swB[(c0 + 3) * 2 + 0])
             +        hd.x * swT[(c0 + 0) * 2 + 0] + hd.y * swT[(c0 + 1) * 2 + 0]
             +        hd.z * swT[(c0 + 2) * 2 + 0] + hd.w * swT[(c0 + 3) * 2 + 0];
    float r1 = inv * (acc.x * swB[(c0 + 0) * 2 + 1] + acc.y * swB[(c0 + 1) * 2 + 1]
                    + acc.z * swB[(c0 + 2) * 2 + 1] + acc.w * swB[(c0 + 3) * 2 + 1])
             +        hd.x * swT[(c0 + 0) * 2 + 1] + hd.y * swT[(c0 + 1) * 2 + 1]
             +        hd.z * swT[(c0 + 2) * 2 + 1] + hd.w * swT[(c0 + 3) * 2 + 1];

    // reduce within each 16-lane group (both groups hold identical full sums)
    #pragma unroll
    for (int o = 8; o > 0; o >>= 1) {
        r0 += __shfl_xor_sync(0xFFFFFFFFu, r0, o);
        r1 += __shfl_xor_sync(0xFFFFFFFFu, r1, o);
    }
    if (lane == 0) {
        out[(long long)warp * DOUT + 0] = r0 + sb[0];
        out[(long long)warp * DOUT + 1] = r1 + sb[1];
    }
}

// ---------------------------------------------------------------------------
extern "C" void kernel_launch(void* const* d_in, const int* in_sizes, int n_in,
                              void* d_out, int out_size)
{
    const float* x   = (const float*)d_in[0];
    const int*   ei  = (const int*)d_in[1];
    const float* ea0 = (const float*)d_in[2];
    const float* ea1 = (const float*)d_in[3];
    const float* W0  = (const float*)d_in[4];
    const float* b0  = (const float*)d_in[5];
    const float* W1  = (const float*)d_in[6];
    const float* b1  = (const float*)d_in[7];
    float* out = (float*)d_out;

    const int N = in_sizes[0] / DIN;
    const int E = in_sizes[1] / 2;

    int *hist_p, *rowstart_p, *cursor_p;
    int2 *perm_p;
    float *agg0_p, *h_p;
    cudaGetSymbolAddress((void**)&hist_p,     g_hist);
    cudaGetSymbolAddress((void**)&rowstart_p, g_rowstart);
    cudaGetSymbolAddress((void**)&cursor_p,   g_cursor);
    cudaGetSymbolAddress((void**)&perm_p,     g_perm);
    cudaGetSymbolAddress((void**)&agg0_p,     g_agg0);
    cudaGetSymbolAddress((void**)&h_p,        g_h);

    cudaMemsetAsync(hist_p, 0, (size_t)N * sizeof(int), 0);
    hist_kernel<<<(E + 255) / 256, 256>>>(ei, hist_p, E);
    scan_kernel<<<1, 1024>>>(hist_p, rowstart_p, cursor_p, N, E);
    build_kernel<<<(E + 255) / 256, 256>>>(ei, cursor_p, perm_p, E);
    agg0_kernel<<<(N * 32 + 255) / 256, 256>>>(x, ea0, perm_p, rowstart_p, agg0_p, N);
    layer0_mm_kernel<<<(N + 63) / 64, 256>>>(x, agg0_p, W0, b0, h_p, N);
    // launch 6: fused layer-1 (half-warp float4, padded batches)
    agg1_fused_kernel<<<(N * 32 + 255) / 256, 256>>>(h_p, ea1, perm_p, rowstart_p,
                                                     W1, b1, out, N);
}